// round 13
// baseline (speedup 1.0000x reference)
#include <cuda_runtime.h>
#include <cuda_bf16.h>
#include <cuda_fp16.h>
#include <cstdint>
#include <math.h>

#define NN 50000
#define NC 10
#define NL 2
#define NE 800000
#define ND 128

#define NTOT (NC * NN + NN)              // flat node slots: 10 class graphs + ori
#define TE   ((size_t)NC * NE + NE)      // total edges per layer (graph + ori)
#define TE4  (TE / 4)
#define CAP  64                          // fixed CSR capacity (deg ~ Poisson(16))

#define GB0 ((NC * NN + 7) / 8)          // 62500 gather_graph blocks
#define GBO ((NN + 7) / 8)               // 6250 gather_ori blocks
#define FB  ((int)((TE4 + 255) / 256))   // 8594 fill blocks
#define COMBO_GRID (9 * FB)              // 1 fill : 8 gather interleave

// ---------------- scratch (device globals; no runtime allocation) ----------
__device__ float  g_bufA[(size_t)NC * NN * ND];   // GCN output (attention input)
__device__ float  g_bufB[(size_t)NC * NN * ND];   // attention+Wv output (layer 0)
__device__ float  g_mixed[(size_t)NC * NN * ND];  // scores @ feat
__device__ __half g_xw[(size_t)NC * NN * ND];     // (X @ W) * dinv[row], fp16
__device__ __half g_oxw[(size_t)NN * ND];
__device__ float  g_ofe[(size_t)NN * ND];
__device__ float  g_qt[NC * ND];                  // Wk @ q[c]
__device__ float  g_dinv[2][NTOT];                // per-layer CSR sets
__device__ int    g_cur[2][NTOT];
__device__ int    g_csr[2][(size_t)NTOT * CAP];
__device__ int    g_board[NN];
__device__ int    g_rel[2][NN];
// pre-transposed ([n][k]) bf16-split weights: [0]=W0 [1]=W1 [2]=Wv
__device__ __nv_bfloat16 g_whi[3][16384];
__device__ __nv_bfloat16 g_wlo[3][16384];

// ---------------- helpers ----------------------------------------------------
__device__ __forceinline__ uint32_t smem_u32(const void* p) {
    uint32_t a;
    asm("{ .reg .u64 t; cvta.to.shared.u64 t, %1; cvt.u32.u64 %0, t; }" : "=r"(a) : "l"(p));
    return a;
}

#define LDSM4(r0, r1, r2, r3, addr) \
    asm volatile("ldmatrix.sync.aligned.m8n8.x4.shared.b16 {%0, %1, %2, %3}, [%4];" \
                 : "=r"(r0), "=r"(r1), "=r"(r2), "=r"(r3) : "r"(addr))

#define MMA16816(d, a, b) \
    asm volatile("mma.sync.aligned.m16n8k16.row.col.f32.bf16.bf16.f32 " \
                 "{%0, %1, %2, %3}, {%4, %5, %6, %7}, {%8, %9}, {%0, %1, %2, %3};" \
                 : "+f"((d)[0]), "+f"((d)[1]), "+f"((d)[2]), "+f"((d)[3]) \
                 : "r"((a)[0]), "r"((a)[1]), "r"((a)[2]), "r"((a)[3]), \
                   "r"((b)[0]), "r"((b)[1]))

__device__ __forceinline__ uint32_t pk_bf(__nv_bfloat16 a, __nv_bfloat16 b) {
    return (uint32_t)__bfloat16_as_ushort(a) | ((uint32_t)__bfloat16_as_ushort(b) << 16);
}

__device__ __forceinline__ float4 ld_h4(const __half* p) {
    uint2 u = *(const uint2*)p;
    __half2 a = *reinterpret_cast<__half2*>(&u.x);
    __half2 b = *reinterpret_cast<__half2*>(&u.y);
    float2 fa = __half22float2(a), fb = __half22float2(b);
    return make_float4(fa.x, fa.y, fb.x, fb.y);
}

// ---------------- mma.sync GEMM, two block segments --------------------------
// seg1: blocks [0, nb1)  -> A1 (fp32) -> C1 (fp32) or H1 (fp16)
// seg2: blocks [nb1, ..) -> A2 (fp32) -> C2 / H2
// out = (A @ W)*rs + bias (opt relu); 3-term bf16 split, fp32 accumulators.
#define PADK 136                      // padded row stride (bf16 elems)
#define ASZ (128 * PADK)              // one tile, elems
#define MM_SMEM (4 * ASZ * 2)         // Ahi, Alo, Bhi, Blo

__global__ void __launch_bounds__(256) gemm_mma(
        const float* __restrict__ A1, const float* __restrict__ rs1,
        float* __restrict__ C1, __half* __restrict__ H1, int M1, int nb1,
        const float* __restrict__ A2, const float* __restrict__ rs2,
        float* __restrict__ C2, __half* __restrict__ H2, int M2,
        const __nv_bfloat16* __restrict__ Bhi_g,
        const __nv_bfloat16* __restrict__ Blo_g,
        const float* __restrict__ bias, int doRelu) {
    extern __shared__ __nv_bfloat16 sb[];
    __nv_bfloat16* Bh = sb + 2 * ASZ;
    __nv_bfloat16* Bl = sb + 3 * ASZ;

    const int tid = threadIdx.x;
    const float* A;
    const float* rowscale;
    float* C;
    __half* Ch;
    int M, row0;
    if ((int)blockIdx.x < nb1) {
        A = A1; rowscale = rs1; C = C1; Ch = H1; M = M1;
        row0 = blockIdx.x * 128;
    } else {
        A = A2; rowscale = rs2; C = C2; Ch = H2; M = M2;
        row0 = (blockIdx.x - nb1) * 128;
    }

    // B tiles
#pragma unroll
    for (int it = 0; it < 8; ++it) {
        int i = tid + it * 256;
        int n = i >> 4, k8 = (i & 15) * 8;
        *(uint4*)(Bh + n * PADK + k8) = ((const uint4*)Bhi_g)[i];
        *(uint4*)(Bl + n * PADK + k8) = ((const uint4*)Blo_g)[i];
    }

    // A tile: fp32 -> bf16 hi/lo
#pragma unroll
    for (int it = 0; it < 16; ++it) {
        int i = tid + it * 256;
        int m = i >> 5, k4 = (i & 31) * 4;
        float4 v = make_float4(0.f, 0.f, 0.f, 0.f);
        int gr = row0 + m;
        if (gr < M) v = *(const float4*)(A + (size_t)gr * 128 + k4);
        __nv_bfloat16 h0 = __float2bfloat16(v.x), h1 = __float2bfloat16(v.y);
        __nv_bfloat16 h2 = __float2bfloat16(v.z), h3 = __float2bfloat16(v.w);
        __nv_bfloat16 l0 = __float2bfloat16(v.x - __bfloat162float(h0));
        __nv_bfloat16 l1 = __float2bfloat16(v.y - __bfloat162float(h1));
        __nv_bfloat16 l2 = __float2bfloat16(v.z - __bfloat162float(h2));
        __nv_bfloat16 l3 = __float2bfloat16(v.w - __bfloat162float(h3));
        uint32_t off = m * PADK + k4;
        *(uint2*)(sb + off)       = make_uint2(pk_bf(h0, h1), pk_bf(h2, h3));
        *(uint2*)(sb + ASZ + off) = make_uint2(pk_bf(l0, l1), pk_bf(l2, l3));
    }
    __syncthreads();

    const int lane = tid & 31, wid = tid >> 5;
    const int wm = wid & 3, wn = wid >> 2;

    float acc[2][8][4];
#pragma unroll
    for (int mt = 0; mt < 2; ++mt)
#pragma unroll
        for (int nt = 0; nt < 8; ++nt)
#pragma unroll
            for (int q = 0; q < 4; ++q) acc[mt][nt][q] = 0.f;

    const uint32_t sbase = smem_u32(sb);
    const int a_row  = wm * 32 + (lane & 15);
    const int a_col  = (lane >> 4) * 8;
    const int b_row  = wn * 64 + ((lane >> 4) << 3) + (lane & 7);
    const int b_col8 = ((lane >> 3) & 1) * 8;

    const uint32_t aoff[3] = {0u, 0u, (uint32_t)ASZ};
    const uint32_t boff[3] = {(uint32_t)(2 * ASZ), (uint32_t)(3 * ASZ), (uint32_t)(2 * ASZ)};

#pragma unroll
    for (int term = 0; term < 3; ++term) {
        uint32_t Ab = sbase + aoff[term] * 2;
        uint32_t Bb = sbase + boff[term] * 2;
#pragma unroll
        for (int kk = 0; kk < 8; ++kk) {
            uint32_t afr[2][4];
#pragma unroll
            for (int mt = 0; mt < 2; ++mt) {
                uint32_t ad = Ab + (uint32_t)(((a_row + mt * 16) * PADK) + kk * 16 + a_col) * 2;
                LDSM4(afr[mt][0], afr[mt][1], afr[mt][2], afr[mt][3], ad);
            }
            uint32_t bfr[8][2];
#pragma unroll
            for (int p = 0; p < 4; ++p) {
                uint32_t bd = Bb + (uint32_t)(((b_row + p * 16) * PADK) + kk * 16 + b_col8) * 2;
                LDSM4(bfr[2 * p][0], bfr[2 * p][1], bfr[2 * p + 1][0], bfr[2 * p + 1][1], bd);
            }
#pragma unroll
            for (int mt = 0; mt < 2; ++mt)
#pragma unroll
                for (int nt = 0; nt < 8; ++nt)
                    MMA16816(acc[mt][nt], afr[mt], bfr[nt]);
        }
    }

    const int rbase = row0 + wm * 32 + (lane >> 2);
    const int cbase = wn * 64 + (lane & 3) * 2;
#pragma unroll
    for (int mt = 0; mt < 2; ++mt) {
        int r1 = rbase + mt * 16, r2 = r1 + 8;
        float rs_1 = 1.f, rs_2 = 1.f;
        if (rowscale) {
            if (r1 < M) rs_1 = rowscale[r1];
            if (r2 < M) rs_2 = rowscale[r2];
        }
#pragma unroll
        for (int nt = 0; nt < 8; ++nt) {
            int c = cbase + nt * 8;
            float b0v = bias ? bias[c] : 0.f;
            float b1v = bias ? bias[c + 1] : 0.f;
            if (r1 < M) {
                float o0 = acc[mt][nt][0] * rs_1 + b0v;
                float o1 = acc[mt][nt][1] * rs_1 + b1v;
                if (doRelu) { o0 = fmaxf(o0, 0.f); o1 = fmaxf(o1, 0.f); }
                if (Ch) *(__half2*)(Ch + (size_t)r1 * 128 + c) = __floats2half2_rn(o0, o1);
                else    *(float2*)(C + (size_t)r1 * 128 + c) = make_float2(o0, o1);
            }
            if (r2 < M) {
                float o2 = acc[mt][nt][2] * rs_2 + b0v;
                float o3 = acc[mt][nt][3] * rs_2 + b1v;
                if (doRelu) { o2 = fmaxf(o2, 0.f); o3 = fmaxf(o3, 0.f); }
                if (Ch) *(__half2*)(Ch + (size_t)r2 * 128 + c) = __floats2half2_rn(o2, o3);
                else    *(float2*)(C + (size_t)r2 * 128 + c) = make_float2(o2, o3);
            }
        }
    }
}

// ---------------- weight prep: transpose + bf16 split, plain [n][k] ---------
__global__ void prep_w(const float* __restrict__ W0, const float* __restrict__ W1,
                       const float* __restrict__ Wv) {
    const float* W = (blockIdx.x == 0) ? W0 : (blockIdx.x == 1) ? W1 : Wv;
    __nv_bfloat16* hi = &g_whi[blockIdx.x][0];
    __nv_bfloat16* lo = &g_wlo[blockIdx.x][0];
    for (int idx = threadIdx.x; idx < 16384; idx += blockDim.x) {
        int n = idx >> 7, k = idx & 127;
        float x = W[k * 128 + n];          // B[n][k] = W[k][n]
        __nv_bfloat16 h = __float2bfloat16(x);
        __nv_bfloat16 l = __float2bfloat16(x - __bfloat162float(h));
        hi[idx] = h;
        lo[idx] = l;
    }
}

// ---------------- CSR helpers -----------------------------------------------
__global__ void zero_cur_all() {
    int i = blockIdx.x * blockDim.x + threadIdx.x;
    if (i < 2 * NTOT) g_cur[0][i] = 0;   // contiguous 2-layer array
}

__device__ __forceinline__ void fill_edges4(int grp, int tid,
                                            const int* __restrict__ ge,
                                            const int* __restrict__ oe,
                                            int layer, int* __restrict__ cur,
                                            int* __restrict__ csr) {
    size_t i = (size_t)grp * 256 + tid;
    if (i >= TE4) return;
    size_t base = i * 4;
    int nodeBase;
    const int* sptr;
    const int* dptr;
    if (base < (size_t)NC * NE) {
        int c = (int)(base / NE);
        int e = (int)(base - (size_t)c * NE);
        sptr = ge + (size_t)((c * NL + layer) * 2 + 0) * NE + e;
        dptr = ge + (size_t)((c * NL + layer) * 2 + 1) * NE + e;
        nodeBase = c * NN;
    } else {
        int e = (int)(base - (size_t)NC * NE);
        sptr = oe + (size_t)(layer * 2 + 0) * NE + e;
        dptr = oe + (size_t)(layer * 2 + 1) * NE + e;
        nodeBase = NC * NN;
    }
    int4 s = *(const int4*)sptr;
    int4 d = *(const int4*)dptr;
    int p;
    p = atomicAdd(&cur[nodeBase + d.x], 1); if (p < CAP) csr[(size_t)(nodeBase + d.x) * CAP + p] = s.x;
    p = atomicAdd(&cur[nodeBase + d.y], 1); if (p < CAP) csr[(size_t)(nodeBase + d.y) * CAP + p] = s.y;
    p = atomicAdd(&cur[nodeBase + d.z], 1); if (p < CAP) csr[(size_t)(nodeBase + d.z) * CAP + p] = s.z;
    p = atomicAdd(&cur[nodeBase + d.w], 1); if (p < CAP) csr[(size_t)(nodeBase + d.w) * CAP + p] = s.w;
}

__global__ void __launch_bounds__(256) fill_only(const int* __restrict__ ge,
                                                 const int* __restrict__ oe,
                                                 int layer, int* cur, int* csr) {
    fill_edges4(blockIdx.x, threadIdx.x, ge, oe, layer, cur, csr);
}

__global__ void dinv_k(const int* __restrict__ cur, float* __restrict__ dinv) {
    int i = blockIdx.x * blockDim.x + threadIdx.x;
    if (i < NTOT) dinv[i] = rsqrtf((float)(1 + cur[i]));   // true degree
}

// ---------------- gather bodies ----------------------------------------------
__device__ __forceinline__ void gather_graph_blk(int g, int w, int lane,
                                                 const __half* __restrict__ xws,
                                                 const float* __restrict__ bias,
                                                 const int* __restrict__ cur,
                                                 const int* __restrict__ csrB,
                                                 const float* __restrict__ dinv,
                                                 float* __restrict__ out) {
    int gw = g * 8 + w;
    if (gw >= NC * NN) return;
    int c = gw / NN;
    int n = gw - c * NN;
    const __half* xwc = xws + (size_t)c * NN * 128;
    float4 acc = ld_h4(xwc + (size_t)n * 128 + lane * 4);
    int cnt = cur[gw];
    if (cnt > CAP) cnt = CAP;
    const int* csr = csrB + (size_t)gw * CAP;
    int j = 0;
    for (; j + 3 < cnt; j += 4) {
        int s0 = csr[j], s1 = csr[j + 1], s2 = csr[j + 2], s3 = csr[j + 3];
        float4 a0 = ld_h4(xwc + (size_t)s0 * 128 + lane * 4);
        float4 a1 = ld_h4(xwc + (size_t)s1 * 128 + lane * 4);
        float4 a2 = ld_h4(xwc + (size_t)s2 * 128 + lane * 4);
        float4 a3 = ld_h4(xwc + (size_t)s3 * 128 + lane * 4);
        acc.x += a0.x + a1.x + a2.x + a3.x;
        acc.y += a0.y + a1.y + a2.y + a3.y;
        acc.z += a0.z + a1.z + a2.z + a3.z;
        acc.w += a0.w + a1.w + a2.w + a3.w;
    }
    for (; j < cnt; ++j) {
        int s0 = csr[j];
        float4 a0 = ld_h4(xwc + (size_t)s0 * 128 + lane * 4);
        acc.x += a0.x; acc.y += a0.y; acc.z += a0.z; acc.w += a0.w;
    }
    float dv = dinv[gw];
    float4 b4 = *(const float4*)(bias + lane * 4);
    float4 o = make_float4(b4.x + acc.x * dv, b4.y + acc.y * dv,
                           b4.z + acc.z * dv, b4.w + acc.w * dv);
    *(float4*)(out + (size_t)gw * 128 + lane * 4) = o;
}

__device__ __forceinline__ void gather_ori_blk(int g, int w, int lane,
                                               const __half* __restrict__ xws,
                                               const float* __restrict__ bias,
                                               const int* __restrict__ cur,
                                               const int* __restrict__ csrB,
                                               const float* __restrict__ dinv,
                                               const int* __restrict__ rel,
                                               float* __restrict__ out, int doRelu) {
    int gw = g * 8 + w;
    if (gw >= NN) return;
    int n = rel[gw];
    int fi = NC * NN + n;
    float4 acc = ld_h4(xws + (size_t)n * 128 + lane * 4);
    int cnt = cur[fi];
    if (cnt > CAP) cnt = CAP;
    const int* csr = csrB + (size_t)fi * CAP;
    int j = 0;
    for (; j + 3 < cnt; j += 4) {
        int s0 = csr[j], s1 = csr[j + 1], s2 = csr[j + 2], s3 = csr[j + 3];
        float4 a0 = ld_h4(xws + (size_t)s0 * 128 + lane * 4);
        float4 a1 = ld_h4(xws + (size_t)s1 * 128 + lane * 4);
        float4 a2 = ld_h4(xws + (size_t)s2 * 128 + lane * 4);
        float4 a3 = ld_h4(xws + (size_t)s3 * 128 + lane * 4);
        acc.x += a0.x + a1.x + a2.x + a3.x;
        acc.y += a0.y + a1.y + a2.y + a3.y;
        acc.z += a0.z + a1.z + a2.z + a3.z;
        acc.w += a0.w + a1.w + a2.w + a3.w;
    }
    for (; j < cnt; ++j) {
        int s0 = csr[j];
        float4 a0 = ld_h4(xws + (size_t)s0 * 128 + lane * 4);
        acc.x += a0.x; acc.y += a0.y; acc.z += a0.z; acc.w += a0.w;
    }
    float dv = dinv[fi];
    float4 b4 = *(const float4*)(bias + lane * 4);
    float4 o = make_float4(b4.x + acc.x * dv, b4.y + acc.y * dv,
                           b4.z + acc.z * dv, b4.w + acc.w * dv);
    if (doRelu) {
        o.x = fmaxf(o.x, 0.f); o.y = fmaxf(o.y, 0.f);
        o.z = fmaxf(o.z, 0.f); o.w = fmaxf(o.w, 0.f);
    }
    *(float4*)(out + (size_t)gw * 128 + lane * 4) = o;
}

// ---------------- combo: interleaved gathers + next-layer fill ---------------
// slot 0 of every 9 blocks: fill for next layer; slots 1-8: gather blocks.
__global__ void __launch_bounds__(256) combo(
        const __half* __restrict__ xw, const __half* __restrict__ oxw,
        const float* __restrict__ bias,
        float* __restrict__ bufA, float* __restrict__ oout, int doReluOri,
        const int* __restrict__ cur, const int* __restrict__ csrB,
        const float* __restrict__ dinv, const int* __restrict__ rel,
        const int* __restrict__ ge, const int* __restrict__ oe,
        int fillLayer, int doFill, int* curN, int* csrN) {
    int grp  = blockIdx.x / 9;
    int slot = blockIdx.x - grp * 9;
    int tid  = threadIdx.x;
    if (slot == 0) {
        if (doFill) fill_edges4(grp, tid, ge, oe, fillLayer, curN, csrN);
        return;
    }
    int g = grp * 8 + slot - 1;
    int w = tid >> 5, lane = tid & 31;
    if (g < GB0) {
        gather_graph_blk(g, w, lane, xw, bias, cur, csrB, dinv, bufA);
    } else {
        gather_ori_blk(g - GB0, w, lane, oxw, bias, cur, csrB, dinv, rel,
                       oout, doReluOri);
    }
}

// ---------------- qt[c] = Wk @ (label[c] @ Wq + bq) -------------------------
__global__ void q_kernel(const float* __restrict__ label,
                         const float* __restrict__ Wq,
                         const float* __restrict__ bq,
                         const float* __restrict__ Wk) {
    __shared__ float Ls[NC * 128];
    __shared__ float Qs[NC * 128];
    int t = threadIdx.x;  // 128 threads
    for (int i = t; i < NC * 128; i += 128) Ls[i] = label[i];
    __syncthreads();
    for (int c = 0; c < NC; ++c) {
        float acc = bq[t];
#pragma unroll 8
        for (int h = 0; h < 128; ++h) acc += Ls[c * 128 + h] * Wq[h * 128 + t];
        Qs[c * 128 + t] = acc;
    }
    __syncthreads();
    float acc[NC];
#pragma unroll
    for (int c = 0; c < NC; ++c) acc[c] = 0.f;
    for (int j = 0; j < 128; ++j) {
        float wv = Wk[t * 128 + j];
#pragma unroll
        for (int c = 0; c < NC; ++c) acc[c] += wv * Qs[c * 128 + j];
    }
#pragma unroll
    for (int c = 0; c < NC; ++c) g_qt[c * 128 + t] = acc[c];
}

// ---------------- attention scores + mix (fp32) ------------------------------
__global__ void __launch_bounds__(256) attn_mix(const float* __restrict__ feat,
                                                float* __restrict__ mixed) {
    __shared__ float qt_s[NC][128];
    __shared__ float s_s[8][NC][NC];
    int tid = threadIdx.x;
    for (int i = tid; i < NC * 128; i += 256) qt_s[i >> 7][i & 127] = g_qt[i];
    __syncthreads();
    int w = tid >> 5, lane = tid & 31;
    int n = blockIdx.x * 8 + w;
    if (n >= NN) return;

    float4 fr[NC];
#pragma unroll
    for (int k = 0; k < NC; ++k)
        fr[k] = *(const float4*)(feat + ((size_t)k * NN + n) * 128 + lane * 4);

#pragma unroll
    for (int c = 0; c < NC; ++c) {
        float4 qc = *(const float4*)(&qt_s[c][lane * 4]);
#pragma unroll
        for (int k = 0; k < NC; ++k) {
            float p = qc.x * fr[k].x + qc.y * fr[k].y + qc.z * fr[k].z + qc.w * fr[k].w;
            p += __shfl_xor_sync(0xffffffffu, p, 16);
            p += __shfl_xor_sync(0xffffffffu, p, 8);
            p += __shfl_xor_sync(0xffffffffu, p, 4);
            p += __shfl_xor_sync(0xffffffffu, p, 2);
            p += __shfl_xor_sync(0xffffffffu, p, 1);
            if (lane == 0) s_s[w][c][k] = p;
        }
    }
    __syncwarp();
    const float scale = 0.08838834764831845f;  // 1/sqrt(128)
    if (lane < NC) {
        float m = -1e30f;
#pragma unroll
        for (int k = 0; k < NC; ++k) m = fmaxf(m, s_s[w][lane][k]);
        float e[NC], sum = 0.f;
#pragma unroll
        for (int k = 0; k < NC; ++k) {
            e[k] = expf((s_s[w][lane][k] - m) * scale);
            sum += e[k];
        }
        float inv = 1.f / sum;
#pragma unroll
        for (int k = 0; k < NC; ++k) s_s[w][lane][k] = e[k] * inv;
    }
    __syncwarp();

    float4 acc[NC];
#pragma unroll
    for (int c = 0; c < NC; ++c) acc[c] = make_float4(0.f, 0.f, 0.f, 0.f);
#pragma unroll
    for (int k = 0; k < NC; ++k) {
        float4 vk = fr[k];
#pragma unroll
        for (int c = 0; c < NC; ++c) {
            float sc = s_s[w][c][k];
            acc[c].x += sc * vk.x; acc[c].y += sc * vk.y;
            acc[c].z += sc * vk.z; acc[c].w += sc * vk.w;
        }
    }
#pragma unroll
    for (int c = 0; c < NC; ++c)
        *(float4*)(mixed + ((size_t)c * NN + n) * 128 + lane * 4) = acc[c];
}

// ---------------- ori-branch relative index --------------------------------
__global__ void board_kernel(const int* __restrict__ src_ids) {
    int i = blockIdx.x * blockDim.x + threadIdx.x;
    if (i < NN) g_board[src_ids[i]] = i;
}
__global__ void rel_kernel(const int* __restrict__ dst_ids, int layer) {
    int i = blockIdx.x * blockDim.x + threadIdx.x;
    if (i < NN) g_rel[layer][i] = g_board[dst_ids[i]];
}

// ---------------- orchestration --------------------------------------------
extern "C" void kernel_launch(void* const* d_in, const int* in_sizes, int n_in,
                              void* d_out, int out_size) {
    const float* gfe0  = (const float*)d_in[0];
    const float* ofe0  = (const float*)d_in[1];
    const float* label = (const float*)d_in[2];
    const float* W0 = (const float*)d_in[3];
    const float* b0 = (const float*)d_in[4];
    const float* W1 = (const float*)d_in[5];
    const float* b1 = (const float*)d_in[6];
    const float* Wq = (const float*)d_in[7];
    const float* bq = (const float*)d_in[8];
    const float* Wk = (const float*)d_in[9];
    const float* Wv = (const float*)d_in[11];
    const float* bv = (const float*)d_in[12];
    const int* ge      = (const int*)d_in[13];
    const int* oe      = (const int*)d_in[14];
    const int* src_ids = (const int*)d_in[15];
    const int* dst_ids = (const int*)d_in[16];
    const float* bl[2] = {b0, b1};

    float* out_gfe = (float*)d_out;
    float* out_ofe = out_gfe + (size_t)NC * NN * ND;

    float *bufA, *bufB, *mixed, *ofeB, *dinv0, *dinv1;
    __half *xw, *oxw;
    int *cur0, *cur1, *csr0, *csr1, *rel0, *rel1;
    __nv_bfloat16 *whi, *wlo;
    cudaGetSymbolAddress((void**)&bufA,  g_bufA);
    cudaGetSymbolAddress((void**)&bufB,  g_bufB);
    cudaGetSymbolAddress((void**)&mixed, g_mixed);
    cudaGetSymbolAddress((void**)&xw,    g_xw);
    cudaGetSymbolAddress((void**)&oxw,   g_oxw);
    cudaGetSymbolAddress((void**)&ofeB,  g_ofe);
    cudaGetSymbolAddress((void**)&dinv0, g_dinv);
    cudaGetSymbolAddress((void**)&cur0,  g_cur);
    cudaGetSymbolAddress((void**)&csr0,  g_csr);
    cudaGetSymbolAddress((void**)&rel0,  g_rel);
    cudaGetSymbolAddress((void**)&whi,   g_whi);
    cudaGetSymbolAddress((void**)&wlo,   g_wlo);
    dinv1 = dinv0 + NTOT;
    cur1  = cur0 + NTOT;
    csr1  = csr0 + (size_t)NTOT * CAP;
    rel1  = rel0 + NN;

    cudaFuncSetAttribute(gemm_mma, cudaFuncAttributeMaxDynamicSharedMemorySize, MM_SMEM);

    const int gBig = (NC * NN + 127) / 128;   // 3907
    const int gOri = (NN + 127) / 128;        // 391

    // ---- startup: weights, q, rel indices (input-only deps) ----
    prep_w<<<3, 256>>>(W0, W1, Wv);
    q_kernel<<<1, 128>>>(label, Wq, bq, Wk);
    board_kernel<<<(NN + 255) / 256, 256>>>(src_ids);
    rel_kernel<<<(NN + 255) / 256, 256>>>(dst_ids, 0);
    board_kernel<<<(NN + 255) / 256, 256>>>(src_ids + NN);
    rel_kernel<<<(NN + 255) / 256, 256>>>(dst_ids + NN, 1);

    // ---- CSR layer 0 (layer 1's fill overlaps with layer-0 gathers) ----
    zero_cur_all<<<(2 * NTOT + 255) / 256, 256>>>();
    fill_only<<<FB, 256>>>(ge, oe, 0, cur0, csr0);
    dinv_k<<<(NTOT + 255) / 256, 256>>>(cur0, dinv0);

    // ================= layer 0 =================
    gemm_mma<<<gBig + gOri, 256, MM_SMEM>>>(
        gfe0, dinv0, nullptr, xw, NC * NN, gBig,
        ofe0, dinv0 + NC * NN, nullptr, oxw, NN,
        whi, wlo, nullptr, 0);
    combo<<<COMBO_GRID, 256>>>(xw, oxw, bl[0], bufA, ofeB, 1,
                               cur0, csr0, dinv0, rel0,
                               ge, oe, 1, 1, cur1, csr1);
    dinv_k<<<(NTOT + 255) / 256, 256>>>(cur1, dinv1);
    attn_mix<<<(NN + 7) / 8, 256>>>(bufA, mixed);
    gemm_mma<<<gBig, 256, MM_SMEM>>>(
        mixed, nullptr, bufB, nullptr, NC * NN, gBig,
        nullptr, nullptr, nullptr, nullptr, 0,
        whi + 2 * 16384, wlo + 2 * 16384, bv, 1);

    // ================= layer 1 =================
    gemm_mma<<<gBig + gOri, 256, MM_SMEM>>>(
        bufB, dinv1, nullptr, xw, NC * NN, gBig,
        ofeB, dinv1 + NC * NN, nullptr, oxw, NN,
        whi + 16384, wlo + 16384, nullptr, 0);
    combo<<<COMBO_GRID, 256>>>(xw, oxw, bl[1], bufA, out_ofe, 0,
                               cur1, csr1, dinv1, rel1,
                               ge, oe, 0, 0, nullptr, nullptr);
    attn_mix<<<(NN + 7) / 8, 256>>>(bufA, mixed);
    gemm_mma<<<gBig, 256, MM_SMEM>>>(
        mixed, nullptr, out_gfe, nullptr, NC * NN, gBig,
        nullptr, nullptr, nullptr, nullptr, 0,
        whi + 2 * 16384, wlo + 2 * 16384, bv, 0);
}

// round 14
// speedup vs baseline: 1.4141x; 1.4141x over previous
#include <cuda_runtime.h>
#include <cuda_bf16.h>
#include <cuda_fp16.h>
#include <cstdint>
#include <math.h>

#define NN 50000
#define NC 10
#define NL 2
#define NE 800000
#define ND 128

#define NTOT (NC * NN + NN)              // flat node slots: 10 class graphs + ori
#define TE   ((size_t)NC * NE + NE)      // total edges per layer (graph + ori)
#define TE4  (TE / 4)
#define CAP  64                          // fixed CSR capacity (deg ~ Poisson(16))

// ---------------- scratch (device globals; no runtime allocation) ----------
__device__ float  g_bufA[(size_t)NC * NN * ND];   // GCN output (attention input)
__device__ float  g_bufB[(size_t)NC * NN * ND];   // attention+Wv output (layer 0)
__device__ float  g_mixed[(size_t)NC * NN * ND];  // scores @ feat
__device__ __half g_xw[(size_t)NC * NN * ND];     // (X @ W) * dinv[row], fp16
__device__ __half g_oxw[(size_t)NN * ND];
__device__ float  g_ofe[(size_t)NN * ND];
__device__ float  g_qt[NC * ND];                  // Wk @ q[c]
__device__ float  g_dinv[NTOT];
__device__ int    g_cur[NTOT];
__device__ int    g_csr[(size_t)NTOT * CAP];
__device__ int    g_board[NN];
__device__ int    g_rel[2][NN];

// pre-transposed ([n][k]) bf16-split weights: [0]=W0 [1]=W1 [2]=Wv
__device__ __nv_bfloat16 g_whi[3][16384];
__device__ __nv_bfloat16 g_wlo[3][16384];

// ---------------- helpers ----------------------------------------------------
__device__ __forceinline__ uint32_t smem_u32(const void* p) {
    uint32_t a;
    asm("{ .reg .u64 t; cvta.to.shared.u64 t, %1; cvt.u32.u64 %0, t; }" : "=r"(a) : "l"(p));
    return a;
}

#define LDSM4(r0, r1, r2, r3, addr) \
    asm volatile("ldmatrix.sync.aligned.m8n8.x4.shared.b16 {%0, %1, %2, %3}, [%4];" \
                 : "=r"(r0), "=r"(r1), "=r"(r2), "=r"(r3) : "r"(addr))

#define MMA16816(d, a, b) \
    asm volatile("mma.sync.aligned.m16n8k16.row.col.f32.bf16.bf16.f32 " \
                 "{%0, %1, %2, %3}, {%4, %5, %6, %7}, {%8, %9}, {%0, %1, %2, %3};" \
                 : "+f"((d)[0]), "+f"((d)[1]), "+f"((d)[2]), "+f"((d)[3]) \
                 : "r"((a)[0]), "r"((a)[1]), "r"((a)[2]), "r"((a)[3]), \
                   "r"((b)[0]), "r"((b)[1]))

__device__ __forceinline__ uint32_t pk_bf(__nv_bfloat16 a, __nv_bfloat16 b) {
    return (uint32_t)__bfloat16_as_ushort(a) | ((uint32_t)__bfloat16_as_ushort(b) << 16);
}

__device__ __forceinline__ float4 ld_h4(const __half* p) {
    uint2 u = *(const uint2*)p;
    __half2 a = *reinterpret_cast<__half2*>(&u.x);
    __half2 b = *reinterpret_cast<__half2*>(&u.y);
    float2 fa = __half22float2(a), fb = __half22float2(b);
    return make_float4(fa.x, fa.y, fb.x, fb.y);
}

// ---------------- mma.sync GEMM, two block segments --------------------------
// seg1: blocks [0, nb1)  -> A1 (fp32) -> C1 (fp32) or H1 (fp16)
// seg2: blocks [nb1, ..) -> A2 (fp32) -> C2 / H2 (skipped if nb1 == gridDim)
// out = (A @ W)*rs + bias (opt relu); 3-term bf16 split, fp32 accumulators.
#define PADK 136                      // padded row stride (bf16 elems)
#define ASZ (128 * PADK)              // one tile, elems
#define MM_SMEM (4 * ASZ * 2)         // Ahi, Alo, Bhi, Blo

__global__ void __launch_bounds__(256) gemm_mma(
        const float* __restrict__ A1, const float* __restrict__ rs1,
        float* __restrict__ C1, __half* __restrict__ H1, int M1, int nb1,
        const float* __restrict__ A2, const float* __restrict__ rs2,
        float* __restrict__ C2, __half* __restrict__ H2, int M2,
        const __nv_bfloat16* __restrict__ Bhi_g,
        const __nv_bfloat16* __restrict__ Blo_g,
        const float* __restrict__ bias, int doRelu) {
    extern __shared__ __nv_bfloat16 sb[];
    __nv_bfloat16* Bh = sb + 2 * ASZ;
    __nv_bfloat16* Bl = sb + 3 * ASZ;

    const int tid = threadIdx.x;
    const float* A;
    const float* rowscale;
    float* C;
    __half* Ch;
    int M, row0;
    if ((int)blockIdx.x < nb1) {
        A = A1; rowscale = rs1; C = C1; Ch = H1; M = M1;
        row0 = blockIdx.x * 128;
    } else {
        A = A2; rowscale = rs2; C = C2; Ch = H2; M = M2;
        row0 = (blockIdx.x - nb1) * 128;
    }

    // B tiles
#pragma unroll
    for (int it = 0; it < 8; ++it) {
        int i = tid + it * 256;
        int n = i >> 4, k8 = (i & 15) * 8;
        *(uint4*)(Bh + n * PADK + k8) = ((const uint4*)Bhi_g)[i];
        *(uint4*)(Bl + n * PADK + k8) = ((const uint4*)Blo_g)[i];
    }

    // A tile: fp32 -> bf16 hi/lo
#pragma unroll
    for (int it = 0; it < 16; ++it) {
        int i = tid + it * 256;
        int m = i >> 5, k4 = (i & 31) * 4;
        float4 v = make_float4(0.f, 0.f, 0.f, 0.f);
        int gr = row0 + m;
        if (gr < M) v = *(const float4*)(A + (size_t)gr * 128 + k4);
        __nv_bfloat16 h0 = __float2bfloat16(v.x), h1 = __float2bfloat16(v.y);
        __nv_bfloat16 h2 = __float2bfloat16(v.z), h3 = __float2bfloat16(v.w);
        __nv_bfloat16 l0 = __float2bfloat16(v.x - __bfloat162float(h0));
        __nv_bfloat16 l1 = __float2bfloat16(v.y - __bfloat162float(h1));
        __nv_bfloat16 l2 = __float2bfloat16(v.z - __bfloat162float(h2));
        __nv_bfloat16 l3 = __float2bfloat16(v.w - __bfloat16_as_ushort(h3) * 0.f - __bfloat162float(h3));
        uint32_t off = m * PADK + k4;
        *(uint2*)(sb + off)       = make_uint2(pk_bf(h0, h1), pk_bf(h2, h3));
        *(uint2*)(sb + ASZ + off) = make_uint2(pk_bf(l0, l1), pk_bf(l2, l3));
    }
    __syncthreads();

    const int lane = tid & 31, wid = tid >> 5;
    const int wm = wid & 3, wn = wid >> 2;

    float acc[2][8][4];
#pragma unroll
    for (int mt = 0; mt < 2; ++mt)
#pragma unroll
        for (int nt = 0; nt < 8; ++nt)
#pragma unroll
            for (int q = 0; q < 4; ++q) acc[mt][nt][q] = 0.f;

    const uint32_t sbase = smem_u32(sb);
    const int a_row  = wm * 32 + (lane & 15);
    const int a_col  = (lane >> 4) * 8;
    const int b_row  = wn * 64 + ((lane >> 4) << 3) + (lane & 7);
    const int b_col8 = ((lane >> 3) & 1) * 8;

    const uint32_t aoff[3] = {0u, 0u, (uint32_t)ASZ};
    const uint32_t boff[3] = {(uint32_t)(2 * ASZ), (uint32_t)(3 * ASZ), (uint32_t)(2 * ASZ)};

#pragma unroll
    for (int term = 0; term < 3; ++term) {
        uint32_t Ab = sbase + aoff[term] * 2;
        uint32_t Bb = sbase + boff[term] * 2;
#pragma unroll
        for (int kk = 0; kk < 8; ++kk) {
            uint32_t afr[2][4];
#pragma unroll
            for (int mt = 0; mt < 2; ++mt) {
                uint32_t ad = Ab + (uint32_t)(((a_row + mt * 16) * PADK) + kk * 16 + a_col) * 2;
                LDSM4(afr[mt][0], afr[mt][1], afr[mt][2], afr[mt][3], ad);
            }
            uint32_t bfr[8][2];
#pragma unroll
            for (int p = 0; p < 4; ++p) {
                uint32_t bd = Bb + (uint32_t)(((b_row + p * 16) * PADK) + kk * 16 + b_col8) * 2;
                LDSM4(bfr[2 * p][0], bfr[2 * p][1], bfr[2 * p + 1][0], bfr[2 * p + 1][1], bd);
            }
#pragma unroll
            for (int mt = 0; mt < 2; ++mt)
#pragma unroll
                for (int nt = 0; nt < 8; ++nt)
                    MMA16816(acc[mt][nt], afr[mt], bfr[nt]);
        }
    }

    const int rbase = row0 + wm * 32 + (lane >> 2);
    const int cbase = wn * 64 + (lane & 3) * 2;
#pragma unroll
    for (int mt = 0; mt < 2; ++mt) {
        int r1 = rbase + mt * 16, r2 = r1 + 8;
        float rs_1 = 1.f, rs_2 = 1.f;
        if (rowscale) {
            if (r1 < M) rs_1 = rowscale[r1];
            if (r2 < M) rs_2 = rowscale[r2];
        }
#pragma unroll
        for (int nt = 0; nt < 8; ++nt) {
            int c = cbase + nt * 8;
            float b0v = bias ? bias[c] : 0.f;
            float b1v = bias ? bias[c + 1] : 0.f;
            if (r1 < M) {
                float o0 = acc[mt][nt][0] * rs_1 + b0v;
                float o1 = acc[mt][nt][1] * rs_1 + b1v;
                if (doRelu) { o0 = fmaxf(o0, 0.f); o1 = fmaxf(o1, 0.f); }
                if (Ch) *(__half2*)(Ch + (size_t)r1 * 128 + c) = __floats2half2_rn(o0, o1);
                else    *(float2*)(C + (size_t)r1 * 128 + c) = make_float2(o0, o1);
            }
            if (r2 < M) {
                float o2 = acc[mt][nt][2] * rs_2 + b0v;
                float o3 = acc[mt][nt][3] * rs_2 + b1v;
                if (doRelu) { o2 = fmaxf(o2, 0.f); o3 = fmaxf(o3, 0.f); }
                if (Ch) *(__half2*)(Ch + (size_t)r2 * 128 + c) = __floats2half2_rn(o2, o3);
                else    *(float2*)(C + (size_t)r2 * 128 + c) = make_float2(o2, o3);
            }
        }
    }
}

// ---------------- weight prep: transpose + bf16 split, plain [n][k] ---------
__global__ void prep_w(const float* __restrict__ W0, const float* __restrict__ W1,
                       const float* __restrict__ Wv) {
    const float* W = (blockIdx.x == 0) ? W0 : (blockIdx.x == 1) ? W1 : Wv;
    __nv_bfloat16* hi = &g_whi[blockIdx.x][0];
    __nv_bfloat16* lo = &g_wlo[blockIdx.x][0];
    for (int idx = threadIdx.x; idx < 16384; idx += blockDim.x) {
        int n = idx >> 7, k = idx & 127;
        float x = W[k * 128 + n];          // B[n][k] = W[k][n]
        __nv_bfloat16 h = __float2bfloat16(x);
        __nv_bfloat16 l = __float2bfloat16(x - __bfloat162float(h));
        hi[idx] = h;
        lo[idx] = l;
    }
}

// ---------------- CSR construction: fixed-capacity int, no count/scan ------
__global__ void zero_cur() {
    int i = blockIdx.x * blockDim.x + threadIdx.x;
    if (i < NTOT) g_cur[i] = 0;
}

__global__ void __launch_bounds__(256) fill_all(const int* __restrict__ ge,
                                                const int* __restrict__ oe,
                                                int layer) {
    size_t i = (size_t)blockIdx.x * blockDim.x + threadIdx.x;
    if (i >= TE4) return;
    size_t base = i * 4;
    int nodeBase;
    const int* sptr;
    const int* dptr;
    if (base < (size_t)NC * NE) {
        int c = (int)(base / NE);
        int e = (int)(base - (size_t)c * NE);
        sptr = ge + (size_t)((c * NL + layer) * 2 + 0) * NE + e;
        dptr = ge + (size_t)((c * NL + layer) * 2 + 1) * NE + e;
        nodeBase = c * NN;
    } else {
        int e = (int)(base - (size_t)NC * NE);
        sptr = oe + (size_t)(layer * 2 + 0) * NE + e;
        dptr = oe + (size_t)(layer * 2 + 1) * NE + e;
        nodeBase = NC * NN;
    }
    int4 s = *(const int4*)sptr;
    int4 d = *(const int4*)dptr;
    int p;
    p = atomicAdd(&g_cur[nodeBase + d.x], 1); if (p < CAP) g_csr[(size_t)(nodeBase + d.x) * CAP + p] = s.x;
    p = atomicAdd(&g_cur[nodeBase + d.y], 1); if (p < CAP) g_csr[(size_t)(nodeBase + d.y) * CAP + p] = s.y;
    p = atomicAdd(&g_cur[nodeBase + d.z], 1); if (p < CAP) g_csr[(size_t)(nodeBase + d.z) * CAP + p] = s.z;
    p = atomicAdd(&g_cur[nodeBase + d.w], 1); if (p < CAP) g_csr[(size_t)(nodeBase + d.w) * CAP + p] = s.w;
}

__global__ void dinv_k() {
    int i = blockIdx.x * blockDim.x + threadIdx.x;
    if (i < NTOT) g_dinv[i] = rsqrtf((float)(1 + g_cur[i]));   // true degree
}

// ---------------- GCN gather (xw fp16, pre-scaled by dinv[src]) -------------
__global__ void __launch_bounds__(256) gather_graph(const __half* __restrict__ xws,
                                                    const float* __restrict__ bias,
                                                    float* __restrict__ out) {
    int gw = blockIdx.x * 8 + (threadIdx.x >> 5);
    if (gw >= NC * NN) return;
    int lane = threadIdx.x & 31;
    int c = gw / NN;
    int n = gw - c * NN;
    const __half* xwc = xws + (size_t)c * NN * 128;
    float4 acc = ld_h4(xwc + (size_t)n * 128 + lane * 4);
    int cnt = g_cur[gw];
    if (cnt > CAP) cnt = CAP;
    const int* csr = g_csr + (size_t)gw * CAP;
    int j = 0;
    for (; j + 3 < cnt; j += 4) {
        int s0 = csr[j], s1 = csr[j + 1], s2 = csr[j + 2], s3 = csr[j + 3];
        float4 a0 = ld_h4(xwc + (size_t)s0 * 128 + lane * 4);
        float4 a1 = ld_h4(xwc + (size_t)s1 * 128 + lane * 4);
        float4 a2 = ld_h4(xwc + (size_t)s2 * 128 + lane * 4);
        float4 a3 = ld_h4(xwc + (size_t)s3 * 128 + lane * 4);
        acc.x += a0.x + a1.x + a2.x + a3.x;
        acc.y += a0.y + a1.y + a2.y + a3.y;
        acc.z += a0.z + a1.z + a2.z + a3.z;
        acc.w += a0.w + a1.w + a2.w + a3.w;
    }
    for (; j < cnt; ++j) {
        int s0 = csr[j];
        float4 a0 = ld_h4(xwc + (size_t)s0 * 128 + lane * 4);
        acc.x += a0.x; acc.y += a0.y; acc.z += a0.z; acc.w += a0.w;
    }
    float dv = g_dinv[gw];
    float4 b4 = *(const float4*)(bias + lane * 4);
    float4 o = make_float4(b4.x + acc.x * dv, b4.y + acc.y * dv,
                           b4.z + acc.z * dv, b4.w + acc.w * dv);
    *(float4*)(out + (size_t)gw * 128 + lane * 4) = o;
}

// ori branch: output row i aggregates node rel[i]; optional relu (fused permute)
__global__ void __launch_bounds__(256) gather_ori(const __half* __restrict__ xws,
                                                  const float* __restrict__ bias,
                                                  const int* __restrict__ rel,
                                                  float* __restrict__ out, int doRelu) {
    int gw = blockIdx.x * 8 + (threadIdx.x >> 5);
    if (gw >= NN) return;
    int lane = threadIdx.x & 31;
    int n = rel[gw];
    int fi = NC * NN + n;
    float4 acc = ld_h4(xws + (size_t)n * 128 + lane * 4);
    int cnt = g_cur[fi];
    if (cnt > CAP) cnt = CAP;
    const int* csr = g_csr + (size_t)fi * CAP;
    int j = 0;
    for (; j + 3 < cnt; j += 4) {
        int s0 = csr[j], s1 = csr[j + 1], s2 = csr[j + 2], s3 = csr[j + 3];
        float4 a0 = ld_h4(xws + (size_t)s0 * 128 + lane * 4);
        float4 a1 = ld_h4(xws + (size_t)s1 * 128 + lane * 4);
        float4 a2 = ld_h4(xws + (size_t)s2 * 128 + lane * 4);
        float4 a3 = ld_h4(xws + (size_t)s3 * 128 + lane * 4);
        acc.x += a0.x + a1.x + a2.x + a3.x;
        acc.y += a0.y + a1.y + a2.y + a3.y;
        acc.z += a0.z + a1.z + a2.z + a3.z;
        acc.w += a0.w + a1.w + a2.w + a3.w;
    }
    for (; j < cnt; ++j) {
        int s0 = csr[j];
        float4 a0 = ld_h4(xws + (size_t)s0 * 128 + lane * 4);
        acc.x += a0.x; acc.y += a0.y; acc.z += a0.z; acc.w += a0.w;
    }
    float dv = g_dinv[fi];
    float4 b4 = *(const float4*)(bias + lane * 4);
    float4 o = make_float4(b4.x + acc.x * dv, b4.y + acc.y * dv,
                           b4.z + acc.z * dv, b4.w + acc.w * dv);
    if (doRelu) {
        o.x = fmaxf(o.x, 0.f); o.y = fmaxf(o.y, 0.f);
        o.z = fmaxf(o.z, 0.f); o.w = fmaxf(o.w, 0.f);
    }
    *(float4*)(out + (size_t)gw * 128 + lane * 4) = o;
}

// ---------------- qt[c] = Wk @ (label[c] @ Wq + bq) -------------------------
__global__ void q_kernel(const float* __restrict__ label,
                         const float* __restrict__ Wq,
                         const float* __restrict__ bq,
                         const float* __restrict__ Wk) {
    __shared__ float Ls[NC * 128];
    __shared__ float Qs[NC * 128];
    int t = threadIdx.x;  // 128 threads
    for (int i = t; i < NC * 128; i += 128) Ls[i] = label[i];
    __syncthreads();
    for (int c = 0; c < NC; ++c) {
        float acc = bq[t];
#pragma unroll 8
        for (int h = 0; h < 128; ++h) acc += Ls[c * 128 + h] * Wq[h * 128 + t];
        Qs[c * 128 + t] = acc;
    }
    __syncthreads();
    float acc[NC];
#pragma unroll
    for (int c = 0; c < NC; ++c) acc[c] = 0.f;
    for (int j = 0; j < 128; ++j) {
        float wv = Wk[t * 128 + j];
#pragma unroll
        for (int c = 0; c < NC; ++c) acc[c] += wv * Qs[c * 128 + j];
    }
#pragma unroll
    for (int c = 0; c < NC; ++c) g_qt[c * 128 + t] = acc[c];
}

// ---------------- attention scores + mix (fp32) ------------------------------
__global__ void __launch_bounds__(256) attn_mix(const float* __restrict__ feat,
                                                float* __restrict__ mixed) {
    __shared__ float qt_s[NC][128];
    __shared__ float s_s[8][NC][NC];
    int tid = threadIdx.x;
    for (int i = tid; i < NC * 128; i += 256) qt_s[i >> 7][i & 127] = g_qt[i];
    __syncthreads();
    int w = tid >> 5, lane = tid & 31;
    int n = blockIdx.x * 8 + w;
    if (n >= NN) return;

    float4 fr[NC];
#pragma unroll
    for (int k = 0; k < NC; ++k)
        fr[k] = *(const float4*)(feat + ((size_t)k * NN + n) * 128 + lane * 4);

#pragma unroll
    for (int c = 0; c < NC; ++c) {
        float4 qc = *(const float4*)(&qt_s[c][lane * 4]);
#pragma unroll
        for (int k = 0; k < NC; ++k) {
            float p = qc.x * fr[k].x + qc.y * fr[k].y + qc.z * fr[k].z + qc.w * fr[k].w;
            p += __shfl_xor_sync(0xffffffffu, p, 16);
            p += __shfl_xor_sync(0xffffffffu, p, 8);
            p += __shfl_xor_sync(0xffffffffu, p, 4);
            p += __shfl_xor_sync(0xffffffffu, p, 2);
            p += __shfl_xor_sync(0xffffffffu, p, 1);
            if (lane == 0) s_s[w][c][k] = p;
        }
    }
    __syncwarp();
    const float scale = 0.08838834764831845f;  // 1/sqrt(128)
    if (lane < NC) {
        float m = -1e30f;
#pragma unroll
        for (int k = 0; k < NC; ++k) m = fmaxf(m, s_s[w][lane][k]);
        float e[NC], sum = 0.f;
#pragma unroll
        for (int k = 0; k < NC; ++k) {
            e[k] = expf((s_s[w][lane][k] - m) * scale);
            sum += e[k];
        }
        float inv = 1.f / sum;
#pragma unroll
        for (int k = 0; k < NC; ++k) s_s[w][lane][k] = e[k] * inv;
    }
    __syncwarp();

    float4 acc[NC];
#pragma unroll
    for (int c = 0; c < NC; ++c) acc[c] = make_float4(0.f, 0.f, 0.f, 0.f);
#pragma unroll
    for (int k = 0; k < NC; ++k) {
        float4 vk = fr[k];
#pragma unroll
        for (int c = 0; c < NC; ++c) {
            float sc = s_s[w][c][k];
            acc[c].x += sc * vk.x; acc[c].y += sc * vk.y;
            acc[c].z += sc * vk.z; acc[c].w += sc * vk.w;
        }
    }
#pragma unroll
    for (int c = 0; c < NC; ++c)
        *(float4*)(mixed + ((size_t)c * NN + n) * 128 + lane * 4) = acc[c];
}

// ---------------- ori-branch relative index --------------------------------
__global__ void board_kernel(const int* __restrict__ src_ids) {
    int i = blockIdx.x * blockDim.x + threadIdx.x;
    if (i < NN) g_board[src_ids[i]] = i;
}
__global__ void rel_kernel(const int* __restrict__ dst_ids, int layer) {
    int i = blockIdx.x * blockDim.x + threadIdx.x;
    if (i < NN) g_rel[layer][i] = g_board[dst_ids[i]];
}

// ---------------- orchestration --------------------------------------------
extern "C" void kernel_launch(void* const* d_in, const int* in_sizes, int n_in,
                              void* d_out, int out_size) {
    const float* gfe0  = (const float*)d_in[0];
    const float* ofe0  = (const float*)d_in[1];
    const float* label = (const float*)d_in[2];
    const float* W0 = (const float*)d_in[3];
    const float* b0 = (const float*)d_in[4];
    const float* W1 = (const float*)d_in[5];
    const float* b1 = (const float*)d_in[6];
    const float* Wq = (const float*)d_in[7];
    const float* bq = (const float*)d_in[8];
    const float* Wk = (const float*)d_in[9];
    const float* Wv = (const float*)d_in[11];
    const float* bv = (const float*)d_in[12];
    const int* ge      = (const int*)d_in[13];
    const int* oe      = (const int*)d_in[14];
    const int* src_ids = (const int*)d_in[15];
    const int* dst_ids = (const int*)d_in[16];
    const float* bl[2] = {b0, b1};

    float* out_gfe = (float*)d_out;
    float* out_ofe = out_gfe + (size_t)NC * NN * ND;

    float *bufA, *bufB, *mixed, *ofeB, *dinv;
    __half *xw, *oxw;
    int *rel0;
    __nv_bfloat16 *whi, *wlo;
    cudaGetSymbolAddress((void**)&bufA,  g_bufA);
    cudaGetSymbolAddress((void**)&bufB,  g_bufB);
    cudaGetSymbolAddress((void**)&mixed, g_mixed);
    cudaGetSymbolAddress((void**)&xw,    g_xw);
    cudaGetSymbolAddress((void**)&oxw,   g_oxw);
    cudaGetSymbolAddress((void**)&ofeB,  g_ofe);
    cudaGetSymbolAddress((void**)&dinv,  g_dinv);
    cudaGetSymbolAddress((void**)&rel0,  g_rel);
    cudaGetSymbolAddress((void**)&whi,   g_whi);
    cudaGetSymbolAddress((void**)&wlo,   g_wlo);
    int* rel1 = rel0 + NN;

    cudaFuncSetAttribute(gemm_mma, cudaFuncAttributeMaxDynamicSharedMemorySize, MM_SMEM);

    const int edgeBlocks4 = (int)((TE4 + 255) / 256);
    const int gBig = (NC * NN + 127) / 128;   // 3907
    const int gOri = (NN + 127) / 128;        // 391

    // ---- startup: weights, q, rel indices (input-only deps) ----
    prep_w<<<3, 256>>>(W0, W1, Wv);
    q_kernel<<<1, 128>>>(label, Wq, bq, Wk);
    board_kernel<<<(NN + 255) / 256, 256>>>(src_ids);
    rel_kernel<<<(NN + 255) / 256, 256>>>(dst_ids, 0);
    board_kernel<<<(NN + 255) / 256, 256>>>(src_ids + NN);
    rel_kernel<<<(NN + 255) / 256, 256>>>(dst_ids + NN, 1);

    const float* cur_g = gfe0;
    const float* cur_o = ofe0;

    for (int layer = 0; layer < 2; ++layer) {
        const float* b = bl[layer];
        const __nv_bfloat16* Whi_l = whi + (size_t)layer * 16384;
        const __nv_bfloat16* Wlo_l = wlo + (size_t)layer * 16384;
        const __nv_bfloat16* Whi_v = whi + (size_t)2 * 16384;
        const __nv_bfloat16* Wlo_v = wlo + (size_t)2 * 16384;
        const int* rel = layer ? rel1 : rel0;
        int relu = (layer == 0);

        // ---- fixed-capacity CSR build: one fill pass, no count/scan ----
        zero_cur<<<(NTOT + 255) / 256, 256>>>();
        fill_all<<<edgeBlocks4, 256>>>(ge, oe, layer);
        dinv_k<<<(NTOT + 255) / 256, 256>>>();

        // ---- merged GEMM: graph segment + ori segment, one launch ----
        gemm_mma<<<gBig + gOri, 256, MM_SMEM>>>(
            cur_g, dinv, nullptr, xw, NC * NN, gBig,
            cur_o, dinv + NC * NN, nullptr, oxw, NN,
            Whi_l, Wlo_l, nullptr, 0);

        // ---- gathers (same shapes as the 1968us champion) ----
        gather_graph<<<(NC * NN + 7) / 8, 256>>>(xw, b, bufA);
        gather_ori<<<(NN + 7) / 8, 256>>>(oxw, b, rel,
                                          relu ? ofeB : out_ofe, relu);

        // ---- attention + Wv GEMM ----
        attn_mix<<<(NN + 7) / 8, 256>>>(bufA, mixed);
        gemm_mma<<<gBig, 256, MM_SMEM>>>(
            mixed, nullptr, relu ? bufB : out_gfe, nullptr, NC * NN, gBig,
            nullptr, nullptr, nullptr, nullptr, 0,
            Whi_v, Wlo_v, bv, relu);

        cur_g = bufB;
        cur_o = ofeB;
    }
}

// round 15
// speedup vs baseline: 1.4335x; 1.0137x over previous
#include <cuda_runtime.h>
#include <cuda_bf16.h>
#include <cuda_fp16.h>
#include <cstdint>
#include <math.h>

#define NN 50000
#define NC 10
#define NL 2
#define NE 800000
#define ND 128

#define NTOT (NC * NN + NN)
#define TE   ((size_t)NC * NE + NE)
#define TE4  (TE / 4)
#define CAP  64

__device__ float  g_bufA[(size_t)NC * NN * ND];
__device__ float  g_bufB[(size_t)NC * NN * ND];
__device__ float  g_mixed[(size_t)NC * NN * ND];
__device__ __half g_xw[(size_t)NC * NN * ND];
__device__ __half g_oxw[(size_t)NN * ND];
__device__ float  g_ofe[(size_t)NN * ND];
__device__ float  g_qt[NC * ND];
__device__ float  g_dinv[NTOT];
__device__ int    g_cur[NTOT];
__device__ int    g_csr[(size_t)NTOT * CAP];
__device__ int    g_board[NN];
__device__ int    g_rel[NN];
__device__ __nv_bfloat16 g_whi[3][16384];
__device__ __nv_bfloat16 g_wlo[3][16384];

__device__ __forceinline__ uint32_t smem_u32(const void* p) {
    uint32_t a;
    asm("{ .reg .u64 t; cvta.to.shared.u64 t, %1; cvt.u32.u64 %0, t; }" : "=r"(a) : "l"(p));
    return a;
}

#define LDSM4(r0, r1, r2, r3, addr) \
    asm volatile("ldmatrix.sync.aligned.m8n8.x4.shared.b16 {%0, %1, %2, %3}, [%4];" \
                 : "=r"(r0), "=r"(r1), "=r"(r2), "=r"(r3) : "r"(addr))

#define MMA16816(d, a, b) \
    asm volatile("mma.sync.aligned.m16n8k16.row.col.f32.bf16.bf16.f32 " \
                 "{%0, %1, %2, %3}, {%4, %5, %6, %7}, {%8, %9}, {%0, %1, %2, %3};" \
                 : "+f"((d)[0]), "+f"((d)[1]), "+f"((d)[2]), "+f"((d)[3]) \
                 : "r"((a)[0]), "r"((a)[1]), "r"((a)[2]), "r"((a)[3]), \
                   "r"((b)[0]), "r"((b)[1]))

__device__ __forceinline__ uint32_t pk_bf(__nv_bfloat16 a, __nv_bfloat16 b) {
    return (uint32_t)__bfloat16_as_ushort(a) | ((uint32_t)__bfloat16_as_ushort(b) << 16);
}

__device__ __forceinline__ float4 ld_h4(const __half* p) {
    uint2 u = *(const uint2*)p;
    __half2 a = *reinterpret_cast<__half2*>(&u.x);
    __half2 b = *reinterpret_cast<__half2*>(&u.y);
    float2 fa = __half22float2(a), fb = __half22float2(b);
    return make_float4(fa.x, fa.y, fb.x, fb.y);
}

#define PADK 136
#define ASZ (128 * PADK)
#define MM_SMEM (4 * ASZ * 2)

__global__ void __launch_bounds__(256) gemm_mma(const float* __restrict__ A,
                                                const __nv_bfloat16* __restrict__ Bhi_g,
                                                const __nv_bfloat16* __restrict__ Blo_g,
                                                const float* __restrict__ bias,
                                                const float* __restrict__ rowscale,
                                                float* __restrict__ C,
                                                __half* __restrict__ Ch, int M,
                                                int doRelu) {
    extern __shared__ __nv_bfloat16 sb[];
    __nv_bfloat16* Bh = sb + 2 * ASZ;
    __nv_bfloat16* Bl = sb + 3 * ASZ;

    const int tid  = threadIdx.x;
    const int row0 = blockIdx.x * 128;

#pragma unroll
    for (int it = 0; it < 8; ++it) {
        int i = tid + it * 256;
        int n = i >> 4, k8 = (i & 15) * 8;
        *(uint4*)(Bh + n * PADK + k8) = ((const uint4*)Bhi_g)[i];
        *(uint4*)(Bl + n * PADK + k8) = ((const uint4*)Blo_g)[i];
    }

#pragma unroll
    for (int it = 0; it < 16; ++it) {
        int i = tid + it * 256;
        int m = i >> 5, k4 = (i & 31) * 4;
        float4 v = make_float4(0.f, 0.f, 0.f, 0.f);
        int gr = row0 + m;
        if (gr < M) v = *(const float4*)(A + (size_t)gr * 128 + k4);
        __nv_bfloat16 h0 = __float2bfloat16(v.x), h1 = __float2bfloat16(v.y);
        __nv_bfloat16 h2 = __float2bfloat16(v.z), h3 = __float2bfloat16(v.w);
        __nv_bfloat16 l0 = __float2bfloat16(v.x - __bfloat162float(h0));
        __nv_bfloat16 l1 = __float2bfloat16(v.y - __bfloat162float(h1));
        __nv_bfloat16 l2 = __float2bfloat16(v.z - __bfloat162float(h2));
        __nv_bfloat16 l3 = __float2bfloat16(v.w - __bfloat162float(h3));
        uint32_t off = m * PADK + k4;
        *(uint2*)(sb + off)       = make_uint2(pk_bf(h0, h1), pk_bf(h2, h3));
        *(uint2*)(sb + ASZ + off) = make_uint2(pk_bf(l0, l1), pk_bf(l2, l3));
    }
    __syncthreads();

    const int lane = tid & 31, wid = tid >> 5;
    const int wm = wid & 3, wn = wid >> 2;

    float acc[2][8][4];
#pragma unroll
    for (int mt = 0; mt < 2; ++mt)
#pragma unroll
        for (int nt = 0; nt < 8; ++nt)
#pragma unroll
            for (int q = 0; q < 4; ++q) acc[mt][nt][q] = 0.f;

    const uint32_t sbase = smem_u32(sb);
    const int a_row  = wm * 32 + (lane & 15);
    const int a_col  = (lane >> 4) * 8;
    const int b_row  = wn * 64 + ((lane >> 4) << 3) + (lane & 7);
    const int b_col8 = ((lane >> 3) & 1) * 8;

    const uint32_t aoff[3] = {0u, 0u, (uint32_t)ASZ};
    const uint32_t boff[3] = {(uint32_t)(2 * ASZ), (uint32_t)(3 * ASZ), (uint32_t)(2 * ASZ)};

#pragma unroll
    for (int term = 0; term < 3; ++term) {
        uint32_t Ab = sbase + aoff[term] * 2;
        uint32_t Bb = sbase + boff[term] * 2;
#pragma unroll
        for (int kk = 0; kk < 8; ++kk) {
            uint32_t afr[2][4];
#pragma unroll
            for (int mt = 0; mt < 2; ++mt) {
                uint32_t ad = Ab + (uint32_t)(((a_row + mt * 16) * PADK) + kk * 16 + a_col) * 2;
                LDSM4(afr[mt][0], afr[mt][1], afr[mt][2], afr[mt][3], ad);
            }
            uint32_t bfr[8][2];
#pragma unroll
            for (int p = 0; p < 4; ++p) {
                uint32_t bd = Bb + (uint32_t)(((b_row + p * 16) * PADK) + kk * 16 + b_col8) * 2;
                LDSM4(bfr[2 * p][0], bfr[2 * p][1], bfr[2 * p + 1][0], bfr[2 * p + 1][1], bd);
            }
#pragma unroll
            for (int mt = 0; mt < 2; ++mt)
#pragma unroll
                for (int nt = 0; nt < 8; ++nt)
                    MMA16816(acc[mt][nt], afr[mt], bfr[nt]);
        }
    }

    const int rbase = row0 + wm * 32 + (lane >> 2);
    const int cbase = wn * 64 + (lane & 3) * 2;
#pragma unroll
    for (int mt = 0; mt < 2; ++mt) {
        int r1 = rbase + mt * 16, r2 = r1 + 8;
        float rs1 = 1.f, rs2 = 1.f;
        if (rowscale) {
            if (r1 < M) rs1 = rowscale[r1];
            if (r2 < M) rs2 = rowscale[r2];
        }
#pragma unroll
        for (int nt = 0; nt < 8; ++nt) {
            int c = cbase + nt * 8;
            float b0v = bias ? bias[c] : 0.f;
            float b1v = bias ? bias[c + 1] : 0.f;
            if (r1 < M) {
                float o0 = acc[mt][nt][0] * rs1 + b0v;
                float o1 = acc[mt][nt][1] * rs1 + b1v;
                if (doRelu) { o0 = fmaxf(o0, 0.f); o1 = fmaxf(o1, 0.f); }
                if (Ch) *(__half2*)(Ch + (size_t)r1 * 128 + c) = __floats2half2_rn(o0, o1);
                else    *(float2*)(C + (size_t)r1 * 128 + c) = make_float2(o0, o1);
            }
            if (r2 < M) {
                float o2 = acc[mt][nt][2] * rs2 + b0v;
                float o3 = acc[mt][nt][3] * rs2 + b1v;
                if (doRelu) { o2 = fmaxf(o2, 0.f); o3 = fmaxf(o3, 0.f); }
                if (Ch) *(__half2*)(Ch + (size_t)r2 * 128 + c) = __floats2half2_rn(o2, o3);
                else    *(float2*)(C + (size_t)r2 * 128 + c) = make_float2(o2, o3);
            }
        }
    }
}

__global__ void prep_w(const float* __restrict__ W0, const float* __restrict__ W1,
                       const float* __restrict__ Wv) {
    const float* W = (blockIdx.x == 0) ? W0 : (blockIdx.x == 1) ? W1 : Wv;
    __nv_bfloat16* hi = &g_whi[blockIdx.x][0];
    __nv_bfloat16* lo = &g_wlo[blockIdx.x][0];
    for (int idx = threadIdx.x; idx < 16384; idx += blockDim.x) {
        int n = idx >> 7, k = idx & 127;
        float x = W[k * 128 + n];
        __nv_bfloat16 h = __float2bfloat16(x);
        __nv_bfloat16 l = __float2bfloat16(x - __bfloat162float(h));
        hi[idx] = h;
        lo[idx] = l;
    }
}

__global__ void zero_cur() {
    int i = blockIdx.x * blockDim.x + threadIdx.x;
    if (i < NTOT) g_cur[i] = 0;
}

__global__ void __launch_bounds__(256) fill_all(const int* __restrict__ ge,
                                                const int* __restrict__ oe,
                                                int layer) {
    size_t i = (size_t)blockIdx.x * blockDim.x + threadIdx.x;
    if (i >= TE4) return;
    size_t base = i * 4;
    int nodeBase;
    const int* sptr;
    const int* dptr;
    if (base < (size_t)NC * NE) {
        int c = (int)(base / NE);
        int e = (int)(base - (size_t)c * NE);
        sptr = ge + (size_t)((c * NL + layer) * 2 + 0) * NE + e;
        dptr = ge + (size_t)((c * NL + layer) * 2 + 1) * NE + e;
        nodeBase = c * NN;
    } else {
        int e = (int)(base - (size_t)NC * NE);
        sptr = oe + (size_t)(layer * 2 + 0) * NE + e;
        dptr = oe + (size_t)(layer * 2 + 1) * NE + e;
        nodeBase = NC * NN;
    }
    int4 s = *(const int4*)sptr;
    int4 d = *(const int4*)dptr;
    int p;
    p = atomicAdd(&g_cur[nodeBase + d.x], 1); if (p < CAP) g_csr[(size_t)(nodeBase + d.x) * CAP + p] = s.x;
    p = atomicAdd(&g_cur[nodeBase + d.y], 1); if (p < CAP) g_csr[(size_t)(nodeBase + d.y) * CAP + p] = s.y;
    p = atomicAdd(&g_cur[nodeBase + d.z], 1); if (p < CAP) g_csr[(size_t)(nodeBase + d.z) * CAP + p] = s.z;
    p = atomicAdd(&g_cur[nodeBase + d.w], 1); if (p < CAP) g_csr[(size_t)(nodeBase + d.w) * CAP + p] = s.w;
}

__global__ void dinv_k() {
    int i = blockIdx.x * blockDim.x + threadIdx.x;
    if (i < NTOT) g_dinv[i] = rsqrtf((float)(1 + g_cur[i]));
}

#define ACC4(acc, a) \
    do { acc.x += a.x; acc.y += a.y; acc.z += a.z; acc.w += a.w; } while (0)

__global__ void __launch_bounds__(256) gather_graph(const __half* __restrict__ xws,
                                                    const float* __restrict__ bias,
                                                    float* __restrict__ out) {
    int gw = blockIdx.x * 8 + (threadIdx.x >> 5);
    if (gw >= NC * NN) return;
    int lane = threadIdx.x & 31;
    int c = gw / NN;
    int n = gw - c * NN;
    const __half* xwc = xws + (size_t)c * NN * 128;
    float4 acc = ld_h4(xwc + (size_t)n * 128 + lane * 4);
    int cnt = g_cur[gw];
    if (cnt > CAP) cnt = CAP;
    const int* csr = g_csr + (size_t)gw * CAP;
    int j = 0;
    for (; j + 7 < cnt; j += 8) {
        int s[8];
#pragma unroll
        for (int q = 0; q < 8; ++q) s[q] = csr[j + q];
        float4 a[8];
#pragma unroll
        for (int q = 0; q < 8; ++q) a[q] = ld_h4(xwc + (size_t)s[q] * 128 + lane * 4);
#pragma unroll
        for (int q = 0; q < 8; ++q) ACC4(acc, a[q]);
    }
    for (; j + 3 < cnt; j += 4) {
        int s0 = csr[j], s1 = csr[j + 1], s2 = csr[j + 2], s3 = csr[j + 3];
        float4 a0 = ld_h4(xwc + (size_t)s0 * 128 + lane * 4);
        float4 a1 = ld_h4(xwc + (size_t)s1 * 128 + lane * 4);
        float4 a2 = ld_h4(xwc + (size_t)s2 * 128 + lane * 4);
        float4 a3 = ld_h4(xwc + (size_t)s3 * 128 + lane * 4);
        ACC4(acc, a0); ACC4(acc, a1); ACC4(acc, a2); ACC4(acc, a3);
    }
    for (; j < cnt; ++j) {
        float4 a0 = ld_h4(xwc + (size_t)csr[j] * 128 + lane * 4);
        ACC4(acc, a0);
    }
    float dv = g_dinv[gw];
    float4 b4 = *(const float4*)(bias + lane * 4);
    float4 o = make_float4(b4.x + acc.x * dv, b4.y + acc.y * dv,
                           b4.z + acc.z * dv, b4.w + acc.w * dv);
    *(float4*)(out + (size_t)gw * 128 + lane * 4) = o;
}

__global__ void __launch_bounds__(256) gather_ori(const __half* __restrict__ xws,
                                                  const float* __restrict__ bias,
                                                  float* __restrict__ out, int doRelu) {
    int gw = blockIdx.x * 8 + (threadIdx.x >> 5);
    if (gw >= NN) return;
    int lane = threadIdx.x & 31;
    int n = g_rel[gw];
    int fi = NC * NN + n;
    float4 acc = ld_h4(xws + (size_t)n * 128 + lane * 4);
    int cnt = g_cur[fi];
    if (cnt > CAP) cnt = CAP;
    const int* csr = g_csr + (size_t)fi * CAP;
    int j = 0;
    for (; j + 7 < cnt; j += 8) {
        int s[8];
#pragma unroll
        for (int q = 0; q < 8; ++q) s[q] = csr[j + q];
        float4 a[8];
#pragma unroll
        for (int q = 0; q < 8; ++q) a[q] = ld_h4(xws + (size_t)s[q] * 128 + lane * 4);
#pragma unroll
        for (int q = 0; q < 8; ++q) ACC4(acc, a[q]);
    }
    for (; j + 3 < cnt; j += 4) {
        int s0 = csr[j], s1 = csr[j + 1], s2 = csr[j + 2], s3 = csr[j + 3];
        float4 a0 = ld_h4(xws + (size_t)s0 * 128 + lane * 4);
        float4 a1 = ld_h4(xws + (size_t)s1 * 128 + lane * 4);
        float4 a2 = ld_h4(xws + (size_t)s2 * 128 + lane * 4);
        float4 a3 = ld_h4(xws + (size_t)s3 * 128 + lane * 4);
        ACC4(acc, a0); ACC4(acc, a1); ACC4(acc, a2); ACC4(acc, a3);
    }
    for (; j < cnt; ++j) {
        float4 a0 = ld_h4(xws + (size_t)csr[j] * 128 + lane * 4);
        ACC4(acc, a0);
    }
    float dv = g_dinv[fi];
    float4 b4 = *(const float4*)(bias + lane * 4);
    float4 o = make_float4(b4.x + acc.x * dv, b4.y + acc.y * dv,
                           b4.z + acc.z * dv, b4.w + acc.w * dv);
    if (doRelu) {
        o.x = fmaxf(o.x, 0.f); o.y = fmaxf(o.y, 0.f);
        o.z = fmaxf(o.z, 0.f); o.w = fmaxf(o.w, 0.f);
    }
    *(float4*)(out + (size_t)gw * 128 + lane * 4) = o;
}

__global__ void q_kernel(const float* __restrict__ label,
                         const float* __restrict__ Wq,
                         const float* __restrict__ bq,
                         const float* __restrict__ Wk) {
    __shared__ float Ls[NC * 128];
    __shared__ float Qs[NC * 128];
    int t = threadIdx.x;
    for (int i = t; i < NC * 128; i += 128) Ls[i] = label[i];
    __syncthreads();
    for (int c = 0; c < NC; ++c) {
        float acc = bq[t];
#pragma unroll 8
        for (int h = 0; h < 128; ++h) acc += Ls[c * 128 + h] * Wq[h * 128 + t];
        Qs[c * 128 + t] = acc;
    }
    __syncthreads();
    float acc[NC];
#pragma unroll
    for (int c = 0; c < NC; ++c) acc[c] = 0.f;
    for (int j = 0; j < 128; ++j) {
        float wv = Wk[t * 128 + j];
#pragma unroll
        for (int c = 0; c < NC; ++c) acc[c] += wv * Qs[c * 128 + j];
    }
#pragma unroll
    for (int c = 0; c < NC; ++c) g_qt[c * 128 + t] = acc[c];
}

__global__ void __launch_bounds__(256) attn_mix(const float* __restrict__ feat,
                                                float* __restrict__ mixed) {
    __shared__ float qt_s[NC][128];
    __shared__ float s_s[8][NC][NC];
    int tid = threadIdx.x;
    for (int i = tid; i < NC * 128; i += 256) qt_s[i >> 7][i & 127] = g_qt[i];
    __syncthreads();
    int w = tid >> 5, lane = tid & 31;
    int n = blockIdx.x * 8 + w;
    if (n >= NN) return;

    float4 fr[NC];
#pragma unroll
    for (int k = 0; k < NC; ++k)
        fr[k] = *(const float4*)(feat + ((size_t)k * NN + n) * 128 + lane * 4);

#pragma unroll
    for (int c = 0; c < NC; ++c) {
        float4 qc = *(const float4*)(&qt_s[c][lane * 4]);
#pragma unroll
        for (int k = 0; k < NC; ++k) {
            float p = qc.x * fr[k].x + qc.y * fr[k].y + qc.z * fr[k].z + qc.w * fr[k].w;
            p += __shfl_xor_sync(0xffffffffu, p, 16);
            p += __shfl_xor_sync(0xffffffffu, p, 8);
            p += __shfl_xor_sync(0xffffffffu, p, 4);
            p += __shfl_xor_sync(0xffffffffu, p, 2);
            p += __shfl_xor_sync(0xffffffffu, p, 1);
            if (lane == 0) s_s[w][c][k] = p;
        }
    }
    __syncwarp();
    const float scale = 0.08838834764831845f;
    if (lane < NC) {
        float m = -1e30f;
#pragma unroll
        for (int k = 0; k < NC; ++k) m = fmaxf(m, s_s[w][lane][k]);
        float e[NC], sum = 0.f;
#pragma unroll
        for (int k = 0; k < NC; ++k) {
            e[k] = expf((s_s[w][lane][k] - m) * scale);
            sum += e[k];
        }
        float inv = 1.f / sum;
#pragma unroll
        for (int k = 0; k < NC; ++k) s_s[w][lane][k] = e[k] * inv;
    }
    __syncwarp();

    float4 acc[NC];
#pragma unroll
    for (int c = 0; c < NC; ++c) acc[c] = make_float4(0.f, 0.f, 0.f, 0.f);
#pragma unroll
    for (int k = 0; k < NC; ++k) {
        float4 vk = fr[k];
#pragma unroll
        for (int c = 0; c < NC; ++c) {
            float sc = s_s[w][c][k];
            acc[c].x += sc * vk.x; acc[c].y += sc * vk.y;
            acc[c].z += sc * vk.z; acc[c].w += sc * vk.w;
        }
    }
#pragma unroll
    for (int c = 0; c < NC; ++c)
        *(float4*)(mixed + ((size_t)c * NN + n) * 128 + lane * 4) = acc[c];
}

__global__ void board_kernel(const int* __restrict__ src_ids) {
    int i = blockIdx.x * blockDim.x + threadIdx.x;
    if (i < NN) g_board[src_ids[i]] = i;
}
__global__ void rel_kernel(const int* __restrict__ dst_ids) {
    int i = blockIdx.x * blockDim.x + threadIdx.x;
    if (i < NN) g_rel[i] = g_board[dst_ids[i]];
}

extern "C" void kernel_launch(void* const* d_in, const int* in_sizes, int n_in,
                              void* d_out, int out_size) {
    const float* gfe0  = (const float*)d_in[0];
    const float* ofe0  = (const float*)d_in[1];
    const float* label = (const float*)d_in[2];
    const float* W0 = (const float*)d_in[3];
    const float* b0 = (const float*)d_in[4];
    const float* W1 = (const float*)d_in[5];
    const float* b1 = (const float*)d_in[6];
    const float* Wq = (const float*)d_in[7];
    const float* bq = (const float*)d_in[8];
    const float* Wk = (const float*)d_in[9];
    const float* Wv = (const float*)d_in[11];
    const float* bv = (const float*)d_in[12];
    const int* ge      = (const int*)d_in[13];
    const int* oe      = (const int*)d_in[14];
    const int* src_ids = (const int*)d_in[15];
    const int* dst_ids = (const int*)d_in[16];
    const float* bl[2] = {b0, b1};

    float* out_gfe = (float*)d_out;
    float* out_ofe = out_gfe + (size_t)NC * NN * ND;

    float *bufA, *bufB, *mixed, *ofeB, *dinv;
    __half *xw, *oxw;
    __nv_bfloat16 *whi, *wlo;
    cudaGetSymbolAddress((void**)&bufA,  g_bufA);
    cudaGetSymbolAddress((void**)&bufB,  g_bufB);
    cudaGetSymbolAddress((void**)&mixed, g_mixed);
    cudaGetSymbolAddress((void**)&xw,    g_xw);
    cudaGetSymbolAddress((void**)&oxw,   g_oxw);
    cudaGetSymbolAddress((void**)&ofeB,  g_ofe);
    cudaGetSymbolAddress((void**)&dinv,  g_dinv);
    cudaGetSymbolAddress((void**)&whi,   g_whi);
    cudaGetSymbolAddress((void**)&wlo,   g_wlo);

    cudaFuncSetAttribute(gemm_mma, cudaFuncAttributeMaxDynamicSharedMemorySize, MM_SMEM);

    prep_w<<<3, 256>>>(W0, W1, Wv);
    q_kernel<<<1, 128>>>(label, Wq, bq, Wk);

    const int edgeBlocks4 = (int)((TE4 + 255) / 256);
    const int gBig = (NC * NN + 127) / 128;
    const int gOri = (NN + 127) / 128;

    const float* cur_g = gfe0;
    const float* cur_o = ofe0;

    for (int layer = 0; layer < 2; ++layer) {
        const float* b = bl[layer];
        const __nv_bfloat16* Whi_l = whi + (size_t)layer * 16384;
        const __nv_bfloat16* Wlo_l = wlo + (size_t)layer * 16384;
        const __nv_bfloat16* Whi_v = whi + (size_t)2 * 16384;
        const __nv_bfloat16* Wlo_v = wlo + (size_t)2 * 16384;
        int relu = (layer == 0);

        zero_cur<<<(NTOT + 255) / 256, 256>>>();
        fill_all<<<edgeBlocks4, 256>>>(ge, oe, layer);
        dinv_k<<<(NTOT + 255) / 256, 256>>>();

        gemm_mma<<<gBig, 256, MM_SMEM>>>(cur_g, Whi_l, Wlo_l, nullptr, dinv,
                                         nullptr, xw, NC * NN, 0);
        gather_graph<<<(NC * NN + 7) / 8, 256>>>(xw, b, bufA);
        attn_mix<<<(NN + 7) / 8, 256>>>(bufA, mixed);
        gemm_mma<<<gBig, 256, MM_SMEM>>>(mixed, Whi_v, Wlo_v, bv, nullptr,
                                         relu ? bufB : out_gfe, nullptr,
                                         NC * NN, relu);
        cur_g = bufB;

        gemm_mma<<<gOri, 256, MM_SMEM>>>(cur_o, Whi_l, Wlo_l, nullptr,
                                         dinv + NC * NN, nullptr, oxw, NN, 0);
        board_kernel<<<(NN + 255) / 256, 256>>>(src_ids + (size_t)layer * NN);
        rel_kernel<<<(NN + 255) / 256, 256>>>(dst_ids + (size_t)layer * NN);
        gather_ori<<<(NN + 7) / 8, 256>>>(oxw, b, relu ? ofeB : out_ofe, relu);
        cur_o = ofeB;
    }
}

// round 16
// speedup vs baseline: 1.4484x; 1.0104x over previous
#include <cuda_runtime.h>
#include <cuda_bf16.h>
#include <cuda_fp16.h>
#include <cstdint>
#include <math.h>

#define NN 50000
#define NC 10
#define NL 2
#define NE 800000
#define ND 128

#define NTOT (NC * NN + NN)
#define TE   ((size_t)NC * NE + NE)
#define TE4  (TE / 4)
#define CAP  64

#define FB  ((int)((TE4 + 255) / 256))       // 8594 fill groups
#define AB  ((NN + 7) / 8)                   // 6250 attention blocks
#define MIXG (((FB + 3) / 4 > (AB + 2) / 3 ? (FB + 3) / 4 : (AB + 2) / 3))
#define MIX_GRID (MIXG * 7)                  // 4 fill : 3 attn interleave

__device__ float  g_bufA[(size_t)NC * NN * ND];
__device__ float  g_bufB[(size_t)NC * NN * ND];
__device__ float  g_mixed[(size_t)NC * NN * ND];
__device__ __half g_xw[(size_t)NC * NN * ND];
__device__ __half g_oxw[(size_t)NN * ND];
__device__ float  g_ofe[(size_t)NN * ND];
__device__ float  g_qt[NC * ND];
__device__ float  g_dinv[2][NTOT];
__device__ int    g_cur[2][NTOT];
__device__ int    g_csr[2][(size_t)NTOT * CAP];
__device__ int    g_board[NN];
__device__ int    g_rel[NN];
__device__ __nv_bfloat16 g_whi[3][16384];
__device__ __nv_bfloat16 g_wlo[3][16384];

__device__ __forceinline__ uint32_t smem_u32(const void* p) {
    uint32_t a;
    asm("{ .reg .u64 t; cvta.to.shared.u64 t, %1; cvt.u32.u64 %0, t; }" : "=r"(a) : "l"(p));
    return a;
}

#define LDSM4(r0, r1, r2, r3, addr) \
    asm volatile("ldmatrix.sync.aligned.m8n8.x4.shared.b16 {%0, %1, %2, %3}, [%4];" \
                 : "=r"(r0), "=r"(r1), "=r"(r2), "=r"(r3) : "r"(addr))

#define MMA16816(d, a, b) \
    asm volatile("mma.sync.aligned.m16n8k16.row.col.f32.bf16.bf16.f32 " \
                 "{%0, %1, %2, %3}, {%4, %5, %6, %7}, {%8, %9}, {%0, %1, %2, %3};" \
                 : "+f"((d)[0]), "+f"((d)[1]), "+f"((d)[2]), "+f"((d)[3]) \
                 : "r"((a)[0]), "r"((a)[1]), "r"((a)[2]), "r"((a)[3]), \
                   "r"((b)[0]), "r"((b)[1]))

__device__ __forceinline__ uint32_t pk_bf(__nv_bfloat16 a, __nv_bfloat16 b) {
    return (uint32_t)__bfloat16_as_ushort(a) | ((uint32_t)__bfloat16_as_ushort(b) << 16);
}

__device__ __forceinline__ float4 ld_h4(const __half* p) {
    uint2 u = *(const uint2*)p;
    __half2 a = *reinterpret_cast<__half2*>(&u.x);
    __half2 b = *reinterpret_cast<__half2*>(&u.y);
    float2 fa = __half22float2(a), fb = __half22float2(b);
    return make_float4(fa.x, fa.y, fb.x, fb.y);
}

#define PADK 136
#define ASZ (128 * PADK)
#define MM_SMEM (4 * ASZ * 2)

__global__ void __launch_bounds__(256) gemm_mma(const float* __restrict__ A,
                                                const __nv_bfloat16* __restrict__ Bhi_g,
                                                const __nv_bfloat16* __restrict__ Blo_g,
                                                const float* __restrict__ bias,
                                                const float* __restrict__ rowscale,
                                                float* __restrict__ C,
                                                __half* __restrict__ Ch, int M,
                                                int doRelu) {
    extern __shared__ __nv_bfloat16 sb[];
    __nv_bfloat16* Bh = sb + 2 * ASZ;
    __nv_bfloat16* Bl = sb + 3 * ASZ;

    const int tid  = threadIdx.x;
    const int row0 = blockIdx.x * 128;

#pragma unroll
    for (int it = 0; it < 8; ++it) {
        int i = tid + it * 256;
        int n = i >> 4, k8 = (i & 15) * 8;
        *(uint4*)(Bh + n * PADK + k8) = ((const uint4*)Bhi_g)[i];
        *(uint4*)(Bl + n * PADK + k8) = ((const uint4*)Blo_g)[i];
    }

#pragma unroll
    for (int it = 0; it < 16; ++it) {
        int i = tid + it * 256;
        int m = i >> 5, k4 = (i & 31) * 4;
        float4 v = make_float4(0.f, 0.f, 0.f, 0.f);
        int gr = row0 + m;
        if (gr < M) v = *(const float4*)(A + (size_t)gr * 128 + k4);
        __nv_bfloat16 h0 = __float2bfloat16(v.x), h1 = __float2bfloat16(v.y);
        __nv_bfloat16 h2 = __float2bfloat16(v.z), h3 = __float2bfloat16(v.w);
        __nv_bfloat16 l0 = __float2bfloat16(v.x - __bfloat162float(h0));
        __nv_bfloat16 l1 = __float2bfloat16(v.y - __bfloat162float(h1));
        __nv_bfloat16 l2 = __float2bfloat16(v.z - __bfloat162float(h2));
        __nv_bfloat16 l3 = __float2bfloat16(v.w - __bfloat162float(h3));
        uint32_t off = m * PADK + k4;
        *(uint2*)(sb + off)       = make_uint2(pk_bf(h0, h1), pk_bf(h2, h3));
        *(uint2*)(sb + ASZ + off) = make_uint2(pk_bf(l0, l1), pk_bf(l2, l3));
    }
    __syncthreads();

    const int lane = tid & 31, wid = tid >> 5;
    const int wm = wid & 3, wn = wid >> 2;

    float acc[2][8][4];
#pragma unroll
    for (int mt = 0; mt < 2; ++mt)
#pragma unroll
        for (int nt = 0; nt < 8; ++nt)
#pragma unroll
            for (int q = 0; q < 4; ++q) acc[mt][nt][q] = 0.f;

    const uint32_t sbase = smem_u32(sb);
    const int a_row  = wm * 32 + (lane & 15);
    const int a_col  = (lane >> 4) * 8;
    const int b_row  = wn * 64 + ((lane >> 4) << 3) + (lane & 7);
    const int b_col8 = ((lane >> 3) & 1) * 8;

    const uint32_t aoff[3] = {0u, 0u, (uint32_t)ASZ};
    const uint32_t boff[3] = {(uint32_t)(2 * ASZ), (uint32_t)(3 * ASZ), (uint32_t)(2 * ASZ)};

#pragma unroll
    for (int term = 0; term < 3; ++term) {
        uint32_t Ab = sbase + aoff[term] * 2;
        uint32_t Bb = sbase + boff[term] * 2;
#pragma unroll
        for (int kk = 0; kk < 8; ++kk) {
            uint32_t afr[2][4];
#pragma unroll
            for (int mt = 0; mt < 2; ++mt) {
                uint32_t ad = Ab + (uint32_t)(((a_row + mt * 16) * PADK) + kk * 16 + a_col) * 2;
                LDSM4(afr[mt][0], afr[mt][1], afr[mt][2], afr[mt][3], ad);
            }
            uint32_t bfr[8][2];
#pragma unroll
            for (int p = 0; p < 4; ++p) {
                uint32_t bd = Bb + (uint32_t)(((b_row + p * 16) * PADK) + kk * 16 + b_col8) * 2;
                LDSM4(bfr[2 * p][0], bfr[2 * p][1], bfr[2 * p + 1][0], bfr[2 * p + 1][1], bd);
            }
#pragma unroll
            for (int mt = 0; mt < 2; ++mt)
#pragma unroll
                for (int nt = 0; nt < 8; ++nt)
                    MMA16816(acc[mt][nt], afr[mt], bfr[nt]);
        }
    }

    const int rbase = row0 + wm * 32 + (lane >> 2);
    const int cbase = wn * 64 + (lane & 3) * 2;
#pragma unroll
    for (int mt = 0; mt < 2; ++mt) {
        int r1 = rbase + mt * 16, r2 = r1 + 8;
        float rs1 = 1.f, rs2 = 1.f;
        if (rowscale) {
            if (r1 < M) rs1 = rowscale[r1];
            if (r2 < M) rs2 = rowscale[r2];
        }
#pragma unroll
        for (int nt = 0; nt < 8; ++nt) {
            int c = cbase + nt * 8;
            float b0v = bias ? bias[c] : 0.f;
            float b1v = bias ? bias[c + 1] : 0.f;
            if (r1 < M) {
                float o0 = acc[mt][nt][0] * rs1 + b0v;
                float o1 = acc[mt][nt][1] * rs1 + b1v;
                if (doRelu) { o0 = fmaxf(o0, 0.f); o1 = fmaxf(o1, 0.f); }
                if (Ch) *(__half2*)(Ch + (size_t)r1 * 128 + c) = __floats2half2_rn(o0, o1);
                else    *(float2*)(C + (size_t)r1 * 128 + c) = make_float2(o0, o1);
            }
            if (r2 < M) {
                float o2 = acc[mt][nt][2] * rs2 + b0v;
                float o3 = acc[mt][nt][3] * rs2 + b1v;
                if (doRelu) { o2 = fmaxf(o2, 0.f); o3 = fmaxf(o3, 0.f); }
                if (Ch) *(__half2*)(Ch + (size_t)r2 * 128 + c) = __floats2half2_rn(o2, o3);
                else    *(float2*)(C + (size_t)r2 * 128 + c) = make_float2(o2, o3);
            }
        }
    }
}

__global__ void prep_w(const float* __restrict__ W0, const float* __restrict__ W1,
                       const float* __restrict__ Wv) {
    const float* W = (blockIdx.x == 0) ? W0 : (blockIdx.x == 1) ? W1 : Wv;
    __nv_bfloat16* hi = &g_whi[blockIdx.x][0];
    __nv_bfloat16* lo = &g_wlo[blockIdx.x][0];
    for (int idx = threadIdx.x; idx < 16384; idx += blockDim.x) {
        int n = idx >> 7, k = idx & 127;
        float x = W[k * 128 + n];
        __nv_bfloat16 h = __float2bfloat16(x);
        __nv_bfloat16 l = __float2bfloat16(x - __bfloat162float(h));
        hi[idx] = h;
        lo[idx] = l;
    }
}

__global__ void zero_cur_all() {
    int i = blockIdx.x * blockDim.x + threadIdx.x;
    if (i < 2 * NTOT) ((int*)g_cur)[i] = 0;
}

__device__ __forceinline__ void fill_edges4(int grp, int tid,
                                            const int* __restrict__ ge,
                                            const int* __restrict__ oe,
                                            int layer, int* __restrict__ cur,
                                            int* __restrict__ csr) {
    size_t i = (size_t)grp * 256 + tid;
    if (i >= TE4) return;
    size_t base = i * 4;
    int nodeBase;
    const int* sptr;
    const int* dptr;
    if (base < (size_t)NC * NE) {
        int c = (int)(base / NE);
        int e = (int)(base - (size_t)c * NE);
        sptr = ge + (size_t)((c * NL + layer) * 2 + 0) * NE + e;
        dptr = ge + (size_t)((c * NL + layer) * 2 + 1) * NE + e;
        nodeBase = c * NN;
    } else {
        int e = (int)(base - (size_t)NC * NE);
        sptr = oe + (size_t)(layer * 2 + 0) * NE + e;
        dptr = oe + (size_t)(layer * 2 + 1) * NE + e;
        nodeBase = NC * NN;
    }
    int4 s = *(const int4*)sptr;
    int4 d = *(const int4*)dptr;
    int p;
    p = atomicAdd(&cur[nodeBase + d.x], 1); if (p < CAP) csr[(size_t)(nodeBase + d.x) * CAP + p] = s.x;
    p = atomicAdd(&cur[nodeBase + d.y], 1); if (p < CAP) csr[(size_t)(nodeBase + d.y) * CAP + p] = s.y;
    p = atomicAdd(&cur[nodeBase + d.z], 1); if (p < CAP) csr[(size_t)(nodeBase + d.z) * CAP + p] = s.z;
    p = atomicAdd(&cur[nodeBase + d.w], 1); if (p < CAP) csr[(size_t)(nodeBase + d.w) * CAP + p] = s.w;
}

__global__ void __launch_bounds__(256) fill_only(const int* __restrict__ ge,
                                                 const int* __restrict__ oe,
                                                 int layer, int* cur, int* csr) {
    fill_edges4(blockIdx.x, threadIdx.x, ge, oe, layer, cur, csr);
}

__global__ void dinv_k(const int* __restrict__ cur, float* __restrict__ dinv) {
    int i = blockIdx.x * blockDim.x + threadIdx.x;
    if (i < NTOT) dinv[i] = rsqrtf((float)(1 + cur[i]));
}

#define ACC4(acc, a) \
    do { acc.x += a.x; acc.y += a.y; acc.z += a.z; acc.w += a.w; } while (0)

__global__ void __launch_bounds__(256) gather_graph(const __half* __restrict__ xws,
                                                    const float* __restrict__ bias,
                                                    const int* __restrict__ curB,
                                                    const int* __restrict__ csrBase,
                                                    const float* __restrict__ dinv,
                                                    float* __restrict__ out) {
    int gw = blockIdx.x * 8 + (threadIdx.x >> 5);
    if (gw >= NC * NN) return;
    int lane = threadIdx.x & 31;
    int c = gw / NN;
    int n = gw - c * NN;
    const __half* xwc = xws + (size_t)c * NN * 128;
    float4 acc = ld_h4(xwc + (size_t)n * 128 + lane * 4);
    int cnt = curB[gw];
    if (cnt > CAP) cnt = CAP;
    const int* csr = csrBase + (size_t)gw * CAP;
    int j = 0;
    for (; j + 7 < cnt; j += 8) {
        int s[8];
#pragma unroll
        for (int q = 0; q < 8; ++q) s[q] = csr[j + q];
        float4 a[8];
#pragma unroll
        for (int q = 0; q < 8; ++q) a[q] = ld_h4(xwc + (size_t)s[q] * 128 + lane * 4);
#pragma unroll
        for (int q = 0; q < 8; ++q) ACC4(acc, a[q]);
    }
    for (; j + 3 < cnt; j += 4) {
        int s0 = csr[j], s1 = csr[j + 1], s2 = csr[j + 2], s3 = csr[j + 3];
        float4 a0 = ld_h4(xwc + (size_t)s0 * 128 + lane * 4);
        float4 a1 = ld_h4(xwc + (size_t)s1 * 128 + lane * 4);
        float4 a2 = ld_h4(xwc + (size_t)s2 * 128 + lane * 4);
        float4 a3 = ld_h4(xwc + (size_t)s3 * 128 + lane * 4);
        ACC4(acc, a0); ACC4(acc, a1); ACC4(acc, a2); ACC4(acc, a3);
    }
    for (; j < cnt; ++j) {
        float4 a0 = ld_h4(xwc + (size_t)csr[j] * 128 + lane * 4);
        ACC4(acc, a0);
    }
    float dv = dinv[gw];
    float4 b4 = *(const float4*)(bias + lane * 4);
    float4 o = make_float4(b4.x + acc.x * dv, b4.y + acc.y * dv,
                           b4.z + acc.z * dv, b4.w + acc.w * dv);
    *(float4*)(out + (size_t)gw * 128 + lane * 4) = o;
}

__global__ void __launch_bounds__(256) gather_ori(const __half* __restrict__ xws,
                                                  const float* __restrict__ bias,
                                                  const int* __restrict__ curB,
                                                  const int* __restrict__ csrBase,
                                                  const float* __restrict__ dinv,
                                                  float* __restrict__ out, int doRelu) {
    int gw = blockIdx.x * 8 + (threadIdx.x >> 5);
    if (gw >= NN) return;
    int lane = threadIdx.x & 31;
    int n = g_rel[gw];
    int fi = NC * NN + n;
    float4 acc = ld_h4(xws + (size_t)n * 128 + lane * 4);
    int cnt = curB[fi];
    if (cnt > CAP) cnt = CAP;
    const int* csr = csrBase + (size_t)fi * CAP;
    int j = 0;
    for (; j + 7 < cnt; j += 8) {
        int s[8];
#pragma unroll
        for (int q = 0; q < 8; ++q) s[q] = csr[j + q];
        float4 a[8];
#pragma unroll
        for (int q = 0; q < 8; ++q) a[q] = ld_h4(xws + (size_t)s[q] * 128 + lane * 4);
#pragma unroll
        for (int q = 0; q < 8; ++q) ACC4(acc, a[q]);
    }
    for (; j + 3 < cnt; j += 4) {
        int s0 = csr[j], s1 = csr[j + 1], s2 = csr[j + 2], s3 = csr[j + 3];
        float4 a0 = ld_h4(xws + (size_t)s0 * 128 + lane * 4);
        float4 a1 = ld_h4(xws + (size_t)s1 * 128 + lane * 4);
        float4 a2 = ld_h4(xws + (size_t)s2 * 128 + lane * 4);
        float4 a3 = ld_h4(xws + (size_t)s3 * 128 + lane * 4);
        ACC4(acc, a0); ACC4(acc, a1); ACC4(acc, a2); ACC4(acc, a3);
    }
    for (; j < cnt; ++j) {
        float4 a0 = ld_h4(xws + (size_t)csr[j] * 128 + lane * 4);
        ACC4(acc, a0);
    }
    float dv = dinv[fi];
    float4 b4 = *(const float4*)(bias + lane * 4);
    float4 o = make_float4(b4.x + acc.x * dv, b4.y + acc.y * dv,
                           b4.z + acc.z * dv, b4.w + acc.w * dv);
    if (doRelu) {
        o.x = fmaxf(o.x, 0.f); o.y = fmaxf(o.y, 0.f);
        o.z = fmaxf(o.z, 0.f); o.w = fmaxf(o.w, 0.f);
    }
    *(float4*)(out + (size_t)gw * 128 + lane * 4) = o;
}

__global__ void q_kernel(const float* __restrict__ label,
                         const float* __restrict__ Wq,
                         const float* __restrict__ bq,
                         const float* __restrict__ Wk) {
    __shared__ float Ls[NC * 128];
    __shared__ float Qs[NC * 128];
    int t = threadIdx.x;
    for (int i = t; i < NC * 128; i += 128) Ls[i] = label[i];
    __syncthreads();
    for (int c = 0; c < NC; ++c) {
        float acc = bq[t];
#pragma unroll 8
        for (int h = 0; h < 128; ++h) acc += Ls[c * 128 + h] * Wq[h * 128 + t];
        Qs[c * 128 + t] = acc;
    }
    __syncthreads();
    float acc[NC];
#pragma unroll
    for (int c = 0; c < NC; ++c) acc[c] = 0.f;
    for (int j = 0; j < 128; ++j) {
        float wv = Wk[t * 128 + j];
#pragma unroll
        for (int c = 0; c < NC; ++c) acc[c] += wv * Qs[c * 128 + j];
    }
#pragma unroll
    for (int c = 0; c < NC; ++c) g_qt[c * 128 + t] = acc[c];
}

// ---- attention (+ optional interleaved next-layer fill) ---------------------
// mode=1: grid = MIX_GRID; per 7 blocks: slots 0-3 fill, slots 4-6 attention.
// mode=0: grid = AB; pure attention.
__global__ void __launch_bounds__(256) attn_mix(const float* __restrict__ feat,
                                                float* __restrict__ mixed,
                                                int mode,
                                                const int* __restrict__ ge,
                                                const int* __restrict__ oe,
                                                int fillLayer,
                                                int* curN, int* csrN) {
    int tid = threadIdx.x;
    int ab;
    if (mode) {
        int grp = blockIdx.x / 7, slot = blockIdx.x - grp * 7;
        if (slot < 4) {
            int f = grp * 4 + slot;
            if (f < FB) fill_edges4(f, tid, ge, oe, fillLayer, curN, csrN);
            return;
        }
        ab = grp * 3 + (slot - 4);
        if (ab >= AB) return;
    } else {
        ab = blockIdx.x;
    }

    __shared__ float qt_s[NC][128];
    __shared__ float s_s[8][NC][NC];
    for (int i = tid; i < NC * 128; i += 256) qt_s[i >> 7][i & 127] = g_qt[i];
    __syncthreads();
    int w = tid >> 5, lane = tid & 31;
    int n = ab * 8 + w;
    if (n >= NN) return;

    float4 fr[NC];
#pragma unroll
    for (int k = 0; k < NC; ++k)
        fr[k] = *(const float4*)(feat + ((size_t)k * NN + n) * 128 + lane * 4);

#pragma unroll
    for (int c = 0; c < NC; ++c) {
        float4 qc = *(const float4*)(&qt_s[c][lane * 4]);
#pragma unroll
        for (int k = 0; k < NC; ++k) {
            float p = qc.x * fr[k].x + qc.y * fr[k].y + qc.z * fr[k].z + qc.w * fr[k].w;
            p += __shfl_xor_sync(0xffffffffu, p, 16);
            p += __shfl_xor_sync(0xffffffffu, p, 8);
            p += __shfl_xor_sync(0xffffffffu, p, 4);
            p += __shfl_xor_sync(0xffffffffu, p, 2);
            p += __shfl_xor_sync(0xffffffffu, p, 1);
            if (lane == 0) s_s[w][c][k] = p;
        }
    }
    __syncwarp();
    const float scale = 0.08838834764831845f;
    if (lane < NC) {
        float m = -1e30f;
#pragma unroll
        for (int k = 0; k < NC; ++k) m = fmaxf(m, s_s[w][lane][k]);
        float e[NC], sum = 0.f;
#pragma unroll
        for (int k = 0; k < NC; ++k) {
            e[k] = expf((s_s[w][lane][k] - m) * scale);
            sum += e[k];
        }
        float inv = 1.f / sum;
#pragma unroll
        for (int k = 0; k < NC; ++k) s_s[w][lane][k] = e[k] * inv;
    }
    __syncwarp();

    float4 acc[NC];
#pragma unroll
    for (int c = 0; c < NC; ++c) acc[c] = make_float4(0.f, 0.f, 0.f, 0.f);
#pragma unroll
    for (int k = 0; k < NC; ++k) {
        float4 vk = fr[k];
#pragma unroll
        for (int c = 0; c < NC; ++c) {
            float sc = s_s[w][c][k];
            acc[c].x += sc * vk.x; acc[c].y += sc * vk.y;
            acc[c].z += sc * vk.z; acc[c].w += sc * vk.w;
        }
    }
#pragma unroll
    for (int c = 0; c < NC; ++c)
        *(float4*)(mixed + ((size_t)c * NN + n) * 128 + lane * 4) = acc[c];
}

__global__ void board_kernel(const int* __restrict__ src_ids) {
    int i = blockIdx.x * blockDim.x + threadIdx.x;
    if (i < NN) g_board[src_ids[i]] = i;
}
__global__ void rel_kernel(const int* __restrict__ dst_ids) {
    int i = blockIdx.x * blockDim.x + threadIdx.x;
    if (i < NN) g_rel[i] = g_board[dst_ids[i]];
}

extern "C" void kernel_launch(void* const* d_in, const int* in_sizes, int n_in,
                              void* d_out, int out_size) {
    const float* gfe0  = (const float*)d_in[0];
    const float* ofe0  = (const float*)d_in[1];
    const float* label = (const float*)d_in[2];
    const float* W0 = (const float*)d_in[3];
    const float* b0 = (const float*)d_in[4];
    const float* W1 = (const float*)d_in[5];
    const float* b1 = (const float*)d_in[6];
    const float* Wq = (const float*)d_in[7];
    const float* bq = (const float*)d_in[8];
    const float* Wk = (const float*)d_in[9];
    const float* Wv = (const float*)d_in[11];
    const float* bv = (const float*)d_in[12];
    const int* ge      = (const int*)d_in[13];
    const int* oe      = (const int*)d_in[14];
    const int* src_ids = (const int*)d_in[15];
    const int* dst_ids = (const int*)d_in[16];
    const float* bl[2] = {b0, b1};

    float* out_gfe = (float*)d_out;
    float* out_ofe = out_gfe + (size_t)NC * NN * ND;

    float *bufA, *bufB, *mixed, *ofeB, *dinv0;
    __half *xw, *oxw;
    int *cur0, *csr0;
    __nv_bfloat16 *whi, *wlo;
    cudaGetSymbolAddress((void**)&bufA,  g_bufA);
    cudaGetSymbolAddress((void**)&bufB,  g_bufB);
    cudaGetSymbolAddress((void**)&mixed, g_mixed);
    cudaGetSymbolAddress((void**)&xw,    g_xw);
    cudaGetSymbolAddress((void**)&oxw,   g_oxw);
    cudaGetSymbolAddress((void**)&ofeB,  g_ofe);
    cudaGetSymbolAddress((void**)&dinv0, g_dinv);
    cudaGetSymbolAddress((void**)&cur0,  g_cur);
    cudaGetSymbolAddress((void**)&csr0,  g_csr);
    cudaGetSymbolAddress((void**)&whi,   g_whi);
    cudaGetSymbolAddress((void**)&wlo,   g_wlo);
    float* dinv1 = dinv0 + NTOT;
    int*   cur1  = cur0 + NTOT;
    int*   csr1  = csr0 + (size_t)NTOT * CAP;

    cudaFuncSetAttribute(gemm_mma, cudaFuncAttributeMaxDynamicSharedMemorySize, MM_SMEM);

    const int gBig = (NC * NN + 127) / 128;
    const int gOri = (NN + 127) / 128;

    prep_w<<<3, 256>>>(W0, W1, Wv);
    q_kernel<<<1, 128>>>(label, Wq, bq, Wk);

    // CSR layer 0 (standalone); layer-1 fill is hidden inside layer-0 attn_mix
    zero_cur_all<<<(2 * NTOT + 255) / 256, 256>>>();
    fill_only<<<FB, 256>>>(ge, oe, 0, cur0, csr0);
    dinv_k<<<(NTOT + 255) / 256, 256>>>(cur0, dinv0);

    // ================= layer 0 =================
    gemm_mma<<<gBig, 256, MM_SMEM>>>(gfe0, whi, wlo, nullptr, dinv0,
                                     nullptr, xw, NC * NN, 0);
    gather_graph<<<(NC * NN + 7) / 8, 256>>>(xw, bl[0], cur0, csr0, dinv0, bufA);
    attn_mix<<<MIX_GRID, 256>>>(bufA, mixed, 1, ge, oe, 1, cur1, csr1);
    dinv_k<<<(NTOT + 255) / 256, 256>>>(cur1, dinv1);
    gemm_mma<<<gBig, 256, MM_SMEM>>>(mixed, whi + 2 * 16384, wlo + 2 * 16384,
                                     bv, nullptr, bufB, nullptr, NC * NN, 1);

    gemm_mma<<<gOri, 256, MM_SMEM>>>(ofe0, whi, wlo, nullptr, dinv0 + NC * NN,
                                     nullptr, oxw, NN, 0);
    board_kernel<<<(NN + 255) / 256, 256>>>(src_ids);
    rel_kernel<<<(NN + 255) / 256, 256>>>(dst_ids);
    gather_ori<<<(NN + 7) / 8, 256>>>(oxw, bl[0], cur0, csr0, dinv0, ofeB, 1);

    // ================= layer 1 =================
    gemm_mma<<<gBig, 256, MM_SMEM>>>(bufB, whi + 16384, wlo + 16384, nullptr,
                                     dinv1, nullptr, xw, NC * NN, 0);
    gather_graph<<<(NC * NN + 7) / 8, 256>>>(xw, bl[1], cur1, csr1, dinv1, bufA);
    attn_mix<<<AB, 256>>>(bufA, mixed, 0, nullptr, nullptr, 0, nullptr, nullptr);
    gemm_mma<<<gBig, 256, MM_SMEM>>>(mixed, whi + 2 * 16384, wlo + 2 * 16384,
                                     bv, nullptr, out_gfe, nullptr, NC * NN, 0);

    gemm_mma<<<gOri, 256, MM_SMEM>>>(ofeB, whi + 16384, wlo + 16384, nullptr,
                                     dinv1 + NC * NN, nullptr, oxw, NN, 0);
    board_kernel<<<(NN + 255) / 256, 256>>>(src_ids + NN);
    rel_kernel<<<(NN + 255) / 256, 256>>>(dst_ids + NN);
    gather_ori<<<(NN + 7) / 8, 256>>>(oxw, bl[1], cur1, csr1, dinv1, out_ofe, 0);
}